// round 2
// baseline (speedup 1.0000x reference)
#include <cuda_runtime.h>

#define NATOMS 10000
#define NEDGES 100000
#define DTOT 40            // 1 + 3 + 9 + 27 uncoupled rows per atom
#define UNC 1280           // DTOT * 32 floats per atom
#define USZ 526            // 1 + 12 + 81 + 432
#define WSZ 2560           // 8*128 + 8*96 + 8*64 + 8*32
#define SSZ 142            // 1 + 6 + 27 + 108 per-edge S scalars
#define AB 4               // atoms per block in output kernel

// scratch (allocation-free rule: __device__ globals)
__device__ float g_uncf[(size_t)NATOMS * UNC];
__device__ float g_pool[(size_t)NATOMS * UNC];
__device__ int   g_count[NATOMS];
__device__ int   g_start[NATOMS + 1];
__device__ int   g_cursor[NATOMS];
__device__ int   g_elist[NEDGES];

// ---------------------------------------------------------------------------
// Counting sort of edges by center atom
// ---------------------------------------------------------------------------
__global__ __launch_bounds__(256)
void k_hist(const int* __restrict__ centers)
{
    int e = blockIdx.x * blockDim.x + threadIdx.x;
    if (e < NEDGES) atomicAdd(&g_count[__ldg(centers + e)], 1);
}

__global__ __launch_bounds__(1024)
void k_scan()
{
    __shared__ int part[1024];
    const int t = threadIdx.x;
    int local[10];
    int s = 0;
    #pragma unroll
    for (int i = 0; i < 10; i++) {
        int idx = t * 10 + i;
        int c = (idx < NATOMS) ? g_count[idx] : 0;
        local[i] = s; s += c;
    }
    part[t] = s;
    __syncthreads();
    for (int off = 1; off < 1024; off <<= 1) {
        int v = (t >= off) ? part[t - off] : 0;
        __syncthreads();
        part[t] += v;
        __syncthreads();
    }
    int excl = (t > 0) ? part[t - 1] : 0;
    #pragma unroll
    for (int i = 0; i < 10; i++) {
        int idx = t * 10 + i;
        if (idx < NATOMS) {
            int v = excl + local[i];
            g_start[idx]  = v;
            g_cursor[idx] = v;
        }
    }
    if (t == 1023) g_start[NATOMS] = part[1023];
}

__global__ __launch_bounds__(256)
void k_scatter(const int* __restrict__ centers)
{
    int e = blockIdx.x * blockDim.x + threadIdx.x;
    if (e < NEDGES) {
        int c = __ldg(centers + e);
        int p = atomicAdd(&g_cursor[c], 1);
        g_elist[p] = e;
    }
}

// ---------------------------------------------------------------------------
// Kernel A: uncouple atom features (one warp per atom)
// ---------------------------------------------------------------------------
__global__ __launch_bounds__(256)
void k_uncouple_feat(const float* __restrict__ f0, const float* __restrict__ f1,
                     const float* __restrict__ f2, const float* __restrict__ f3,
                     const float* __restrict__ U0, const float* __restrict__ U1,
                     const float* __restrict__ U2, const float* __restrict__ U3)
{
    __shared__ float Ush[USZ];
    for (int i = threadIdx.x; i < USZ; i += blockDim.x) {
        float v;
        if (i < 1)       v = U0[i];
        else if (i < 13) v = U1[i - 1];
        else if (i < 94) v = U2[i - 13];
        else             v = U3[i - 94];
        Ush[i] = v;
    }
    __syncthreads();

    const int gw   = (blockIdx.x * blockDim.x + threadIdx.x) >> 5;
    const int lane = threadIdx.x & 31;
    if (gw >= NATOMS) return;
    const int a = gw;

    const float* feats[4] = {f0, f1, f2, f3};
    const int KK[4]   = {128, 96, 64, 32};
    const int LOv[4]  = {96, 64, 32, 0};
    const int DL[4]   = {1, 3, 9, 27};
    const int DOFF[4] = {0, 1, 4, 13};
    const int MLv[4]  = {1, 4, 9, 16};
    const int UOFF[4] = {0, 1, 13, 94};

    #pragma unroll
    for (int l = 0; l < 4; l++) {
        float F[16];
        int m = 0;
        #pragma unroll
        for (int lp = 0; lp <= l; lp++) {
            const float* fp = feats[lp];
            const int K = KK[lp];
            long base = (long)a * (2 * lp + 1) * K + LOv[l] + lane;
            #pragma unroll
            for (int mp = 0; mp < 2 * lp + 1; mp++)
                F[m++] = __ldg(fp + base + (long)mp * K);
        }
        float* ob = g_uncf + (long)a * UNC + DOFF[l] * 32 + lane;
        #pragma unroll
        for (int d = 0; d < DL[l]; d++) {
            float acc = 0.f;
            #pragma unroll
            for (int mm = 0; mm < MLv[l]; mm++)
                acc += Ush[UOFF[l] + d * MLv[l] + mm] * F[mm];
            ob[d * 32] = acc;
        }
    }
}

// ---------------------------------------------------------------------------
// Kernel B': one warp per center atom.  Iterates the atom's sorted edge list,
// accumulates the 40 uncoupled rows in registers, single plain store at end.
// No atomics anywhere in the hot path.
// ---------------------------------------------------------------------------
__global__ __launch_bounds__(256)
void k_edge_atom(const float* __restrict__ r,
                 const float* __restrict__ sh0, const float* __restrict__ sh1,
                 const float* __restrict__ sh2, const float* __restrict__ sh3,
                 const float* __restrict__ W0, const float* __restrict__ W1,
                 const float* __restrict__ W2, const float* __restrict__ W3,
                 const float* __restrict__ U0, const float* __restrict__ U1,
                 const float* __restrict__ U2, const float* __restrict__ U3,
                 const int* __restrict__ neighbors)
{
    __shared__ float Wsh[WSZ];
    __shared__ float Ush[USZ];
    __shared__ float Ssh[8 * SSZ];   // 8 warps per block

    for (int i = threadIdx.x; i < WSZ; i += blockDim.x) {
        float v;
        if (i < 1024)      v = W0[i];
        else if (i < 1792) v = W1[i - 1024];
        else if (i < 2304) v = W2[i - 1792];
        else               v = W3[i - 2304];
        Wsh[i] = v;
    }
    for (int i = threadIdx.x; i < USZ; i += blockDim.x) {
        float v;
        if (i < 1)       v = U0[i];
        else if (i < 13) v = U1[i - 1];
        else if (i < 94) v = U2[i - 13];
        else             v = U3[i - 94];
        Ush[i] = v;
    }
    __syncthreads();

    const int lane = threadIdx.x & 31;
    const int wid  = threadIdx.x >> 5;
    float* Sw = Ssh + wid * SSZ;

    const int a = (blockIdx.x * blockDim.x + threadIdx.x) >> 5;   // grid sized exactly
    const int beg = g_start[a];
    const int end = g_start[a + 1];

    float acc[DTOT];
    #pragma unroll
    for (int d = 0; d < DTOT; d++) acc[d] = 0.f;

    const float PI = 3.14159265358979323846f;
    const int KK[4]   = {128, 96, 64, 32};
    const int LOv[4]  = {96, 64, 32, 0};
    const int DL[4]   = {1, 3, 9, 27};
    const int DOFF[4] = {0, 1, 4, 13};
    const int WOFF[4] = {0, 1024, 1792, 2304};
    const int SOFF[4] = {0, 1, 7, 34};

    for (int j = beg; j < end; j++) {
        const int e = __ldg(&g_elist[j]);

        const float rr = __ldg(r + e);
        const float t  = PI * (rr * 0.2f);      // pi * r / CUTOFF
        float s1, c1;
        sincosf(t, &s1, &c1);
        const float ctc  = (t <= PI) ? c1 : -1.f;     // cos(pi*clip(x,0,1))
        const float pref = 0.5f * (ctc + 1.f) / (rr + 1e-6f);
        float rb[8];
        rb[0] = s1 * pref;
        {
            const float twoc = 2.f * c1;
            float sp = 0.f, sc = s1;
            #pragma unroll
            for (int n = 1; n < 8; n++) {             // sin((n+1)t) recurrence
                float sn = twoc * sc - sp;
                sp = sc; sc = sn;
                rb[n] = sn * pref;
            }
        }

        float shv[16];
        shv[0] = __ldg(sh0 + e);
        #pragma unroll
        for (int mp = 0; mp < 3; mp++) shv[1 + mp] = __ldg(sh1 + (long)e * 3 + mp);
        #pragma unroll
        for (int mp = 0; mp < 5; mp++) shv[4 + mp] = __ldg(sh2 + (long)e * 5 + mp);
        #pragma unroll
        for (int mp = 0; mp < 7; mp++) shv[9 + mp] = __ldg(sh3 + (long)e * 7 + mp);

        // per-edge scalars S[l, d, lp] = sum_m' U_l[d, lp^2+m'] * sh[lp, m']
        for (int p = lane; p < SSZ; p += 32) {
            int uo, ml, d, lp;
            if (p < 1)       { uo = 0;  ml = 1;  d = 0;          lp = 0; }
            else if (p < 7)  { int q = p - 1;  uo = 1;  ml = 4;  d = q >> 1; lp = q & 1; }
            else if (p < 34) { int q = p - 7;  uo = 13; ml = 9;  d = q / 3;  lp = q - 3 * (q / 3); }
            else             { int q = p - 34; uo = 94; ml = 16; d = q >> 2; lp = q & 3; }
            const float* Ur = Ush + uo + d * ml + lp * lp;
            float s = 0.f;
            for (int mp = 0; mp < 2 * lp + 1; mp++)
                s += Ur[mp] * shv[lp * lp + mp];
            Sw[p] = s;
        }
        __syncwarp();

        const int nbr = __ldg(neighbors + e);
        const float* fb = g_uncf + (long)nbr * UNC + lane;
        float fbv[DTOT];
        #pragma unroll
        for (int d = 0; d < DTOT; d++) fbv[d] = __ldg(fb + d * 32);

        #pragma unroll
        for (int l = 0; l < 4; l++) {
            float rad[4];
            #pragma unroll
            for (int lp = 0; lp <= l; lp++) {
                const float* w = Wsh + WOFF[lp] + LOv[l] + lane;
                float a2 = 0.f;
                #pragma unroll
                for (int n = 0; n < 8; n++) a2 += rb[n] * w[n * KK[lp]];
                rad[lp] = a2;
            }
            const float* Sl = Sw + SOFF[l];
            #pragma unroll
            for (int d = 0; d < DL[l]; d++) {
                float u = 0.f;
                #pragma unroll
                for (int lp = 0; lp <= l; lp++)
                    u += Sl[d * (l + 1) + lp] * rad[lp];
                acc[DOFF[l] + d] += u * fbv[DOFF[l] + d];
            }
        }
        __syncwarp();   // protect Sw reuse
    }

    float* pb = g_pool + (long)a * UNC + lane;
    #pragma unroll
    for (int d = 0; d < DTOT; d++) pb[d * 32] = acc[d];
}

// ---------------------------------------------------------------------------
// Kernel C: per atom — couple pooled with U, concat into cat_l [2l+1, K_l],
// out_l = feat_l + cat_l @ Wlin_l.  AB atoms per 128-thread block.
// ---------------------------------------------------------------------------
__global__ __launch_bounds__(128)
void k_output(const float* __restrict__ f0, const float* __restrict__ f1,
              const float* __restrict__ f2, const float* __restrict__ f3,
              const float* __restrict__ U0, const float* __restrict__ U1,
              const float* __restrict__ U2, const float* __restrict__ U3,
              const float* __restrict__ L0, const float* __restrict__ L1,
              const float* __restrict__ L2, const float* __restrict__ L3,
              float* __restrict__ out)
{
    __shared__ float Ush[USZ];
    __shared__ float Psh[AB * UNC];
    __shared__ float Csh[AB * 960];
    const int tid = threadIdx.x;

    for (int i = tid; i < USZ; i += 128) {
        float v;
        if (i < 1)       v = U0[i];
        else if (i < 13) v = U1[i - 1];
        else if (i < 94) v = U2[i - 13];
        else             v = U3[i - 94];
        Ush[i] = v;
    }
    const int a0 = blockIdx.x * AB;
    for (int i = tid; i < AB * UNC; i += 128)
        Psh[i] = g_pool[(long)a0 * UNC + i];
    __syncthreads();

    for (int idx = tid; idx < AB * 960; idx += 128) {
        const int a2 = idx / 960;
        const int ii = idx - 960 * a2;
        int l, co, Kl;
        if (ii < 128)      { l = 0; co = 0;   Kl = 128; }
        else if (ii < 416) { l = 1; co = 128; Kl = 96;  }
        else if (ii < 736) { l = 2; co = 416; Kl = 64;  }
        else               { l = 3; co = 736; Kl = 32;  }
        const int loc = ii - co;
        const int m   = loc / Kl;
        const int ch  = loc - m * Kl;
        const int b   = ch >> 5;
        const int c   = ch & 31;
        const int lp  = l + b;
        const int mm  = l * l + m;
        int uo, ml, dof, dc;
        if (lp == 0)      { uo = 0;  ml = 1;  dof = 0;  dc = 1;  }
        else if (lp == 1) { uo = 1;  ml = 4;  dof = 1;  dc = 3;  }
        else if (lp == 2) { uo = 13; ml = 9;  dof = 4;  dc = 9;  }
        else              { uo = 94; ml = 16; dof = 13; dc = 27; }
        const float* pp = Psh + a2 * UNC + dof * 32 + c;
        const float* uu = Ush + uo + mm;
        float acc = 0.f;
        for (int d = 0; d < dc; d++) acc += uu[d * ml] * pp[d * 32];
        Csh[idx] = acc;
    }
    __syncthreads();

    // l=0: [AB x 1 x 128] @ [128 x 128]
    {
        const int q = tid;
        float acc[AB] = {0.f, 0.f, 0.f, 0.f};
        for (int k = 0; k < 128; k++) {
            const float w = __ldg(L0 + k * 128 + q);
            #pragma unroll
            for (int a2 = 0; a2 < AB; a2++) acc[a2] += Csh[a2 * 960 + k] * w;
        }
        #pragma unroll
        for (int a2 = 0; a2 < AB; a2++) {
            const long a = a0 + a2;
            out[a * 128 + q] = __ldg(f0 + a * 128 + q) + acc[a2];
        }
    }
    // l=1: [AB x 3 x 96] @ [96 x 96]
    if (tid < 96) {
        const int q = tid;
        float acc[AB][3] = {};
        for (int k = 0; k < 96; k++) {
            const float w = __ldg(L1 + k * 96 + q);
            #pragma unroll
            for (int a2 = 0; a2 < AB; a2++)
                #pragma unroll
                for (int m = 0; m < 3; m++)
                    acc[a2][m] += Csh[a2 * 960 + 128 + m * 96 + k] * w;
        }
        #pragma unroll
        for (int a2 = 0; a2 < AB; a2++) {
            const long a = a0 + a2;
            #pragma unroll
            for (int m = 0; m < 3; m++)
                out[1280000 + (a * 3 + m) * 96 + q] =
                    __ldg(f1 + (a * 3 + m) * 96 + q) + acc[a2][m];
        }
    }
    // l=2: [AB x 5 x 64] @ [64 x 64]
    {
        const int grp = tid >> 6, q = tid & 63;
        float acc[2][5] = {};
        for (int k = 0; k < 64; k++) {
            const float w = __ldg(L2 + k * 64 + q);
            #pragma unroll
            for (int j = 0; j < 2; j++)
                #pragma unroll
                for (int m = 0; m < 5; m++)
                    acc[j][m] += Csh[(grp * 2 + j) * 960 + 416 + m * 64 + k] * w;
        }
        #pragma unroll
        for (int j = 0; j < 2; j++) {
            const long a = a0 + grp * 2 + j;
            #pragma unroll
            for (int m = 0; m < 5; m++)
                out[4160000 + (a * 5 + m) * 64 + q] =
                    __ldg(f2 + (a * 5 + m) * 64 + q) + acc[j][m];
        }
    }
    // l=3: [AB x 7 x 32] @ [32 x 32]
    {
        const int grp = tid >> 5, q = tid & 31;
        float acc[7] = {};
        for (int k = 0; k < 32; k++) {
            const float w = __ldg(L3 + k * 32 + q);
            #pragma unroll
            for (int m = 0; m < 7; m++)
                acc[m] += Csh[grp * 960 + 736 + m * 32 + k] * w;
        }
        const long a = a0 + grp;
        #pragma unroll
        for (int m = 0; m < 7; m++)
            out[7360000 + (a * 7 + m) * 32 + q] =
                __ldg(f3 + (a * 7 + m) * 32 + q) + acc[m];
    }
}

// ---------------------------------------------------------------------------
// Launch.  Input binding by element count + occurrence order (robust to
// either metadata layout).
// ---------------------------------------------------------------------------
extern "C" void kernel_launch(void* const* d_in, const int* in_sizes, int n_in,
                              void* d_out, int out_size)
{
    const float *r = 0, *sh0 = 0, *sh1 = 0, *sh2 = 0, *sh3 = 0;
    const float *f0 = 0, *f1 = 0, *f2 = 0, *f3 = 0;
    const float *W0 = 0, *W1 = 0, *W2 = 0, *W3 = 0;
    const float *U0 = 0, *U1 = 0, *U2 = 0, *U3 = 0;
    const float *L0 = 0, *L1 = 0, *L2 = 0, *L3 = 0;
    const int *centers = 0, *neighbors = 0;

    int n100k = 0, n1024 = 0;
    for (int i = 0; i < n_in; i++) {
        const void* p = d_in[i];
        switch (in_sizes[i]) {
            case 100000:
                if (n100k == 0)      r = (const float*)p;
                else if (n100k == 1) sh0 = (const float*)p;
                else if (n100k == 2) centers = (const int*)p;
                else                 neighbors = (const int*)p;
                n100k++;
                break;
            case 300000: sh1 = (const float*)p; break;
            case 500000: sh2 = (const float*)p; break;
            case 700000: sh3 = (const float*)p; break;
            case 1280000: f0 = (const float*)p; break;
            case 2880000: f1 = (const float*)p; break;
            case 3200000: f2 = (const float*)p; break;
            case 2240000: f3 = (const float*)p; break;
            case 768: W1 = (const float*)p; break;
            case 512: W2 = (const float*)p; break;
            case 256: W3 = (const float*)p; break;
            case 1:   U0 = (const float*)p; break;
            case 12:  U1 = (const float*)p; break;
            case 81:  U2 = (const float*)p; break;
            case 432: U3 = (const float*)p; break;
            case 16384: L0 = (const float*)p; break;
            case 9216:  L1 = (const float*)p; break;
            case 4096:  L2 = (const float*)p; break;
            case 1024:
                if (n1024 == 0) W0 = (const float*)p;
                else            L3 = (const float*)p;
                n1024++;
                break;
            default: break;
        }
    }
    float* out = (float*)d_out;

    void* cntPtr = 0;
    cudaGetSymbolAddress(&cntPtr, g_count);
    cudaMemsetAsync(cntPtr, 0, NATOMS * sizeof(int));

    k_hist<<<(NEDGES + 255) / 256, 256>>>(centers);
    k_scan<<<1, 1024>>>();
    k_scatter<<<(NEDGES + 255) / 256, 256>>>(centers);

    k_uncouple_feat<<<(NATOMS * 32 + 255) / 256, 256>>>(f0, f1, f2, f3, U0, U1, U2, U3);
    k_edge_atom<<<(NATOMS * 32) / 256, 256>>>(r, sh0, sh1, sh2, sh3,
                                              W0, W1, W2, W3,
                                              U0, U1, U2, U3, neighbors);
    k_output<<<NATOMS / AB, 128>>>(f0, f1, f2, f3, U0, U1, U2, U3,
                                   L0, L1, L2, L3, out);
}

// round 3
// speedup vs baseline: 1.0612x; 1.0612x over previous
#include <cuda_runtime.h>

#define NATOMS 10000
#define NEDGES 100000
#define DTOT 40            // 1 + 3 + 9 + 27 uncoupled rows per atom
#define UNC 1280           // DTOT * 32 floats per atom
#define USZ 526            // 1 + 12 + 81 + 432
#define SSZ 142            // 1 + 6 + 27 + 108 per-edge S scalars
#define SPAD 160           // 40 rows * 4 padded
#define AB 4               // atoms per block in output kernel

// scratch (allocation-free rule: __device__ globals)
__device__ float g_uncf[(size_t)NATOMS * UNC];
__device__ float g_pool[(size_t)NATOMS * UNC];

__global__ void k_nop() {}

__global__ __launch_bounds__(256)
void k_zero()
{
    float4 z = make_float4(0.f, 0.f, 0.f, 0.f);
    float4* p = reinterpret_cast<float4*>(g_pool);
    const int n = NATOMS * UNC / 4;
    for (int i = blockIdx.x * blockDim.x + threadIdx.x; i < n; i += gridDim.x * blockDim.x)
        p[i] = z;
}

// ---------------------------------------------------------------------------
// Kernel A: uncouple atom features (one warp per atom)
// ---------------------------------------------------------------------------
__global__ __launch_bounds__(256)
void k_uncouple_feat(const float* __restrict__ f0, const float* __restrict__ f1,
                     const float* __restrict__ f2, const float* __restrict__ f3,
                     const float* __restrict__ U0, const float* __restrict__ U1,
                     const float* __restrict__ U2, const float* __restrict__ U3)
{
    __shared__ float Ush[USZ];
    for (int i = threadIdx.x; i < USZ; i += blockDim.x) {
        float v;
        if (i < 1)       v = U0[i];
        else if (i < 13) v = U1[i - 1];
        else if (i < 94) v = U2[i - 13];
        else             v = U3[i - 94];
        Ush[i] = v;
    }
    __syncthreads();

    const int gw   = (blockIdx.x * blockDim.x + threadIdx.x) >> 5;
    const int lane = threadIdx.x & 31;
    if (gw >= NATOMS) return;
    const int a = gw;

    const float* feats[4] = {f0, f1, f2, f3};
    const int KK[4]   = {128, 96, 64, 32};
    const int LOv[4]  = {96, 64, 32, 0};
    const int DL[4]   = {1, 3, 9, 27};
    const int DOFF[4] = {0, 1, 4, 13};
    const int MLv[4]  = {1, 4, 9, 16};
    const int UOFF[4] = {0, 1, 13, 94};

    #pragma unroll
    for (int l = 0; l < 4; l++) {
        float F[16];
        int m = 0;
        #pragma unroll
        for (int lp = 0; lp <= l; lp++) {
            const float* fp = feats[lp];
            const int K = KK[lp];
            long base = (long)a * (2 * lp + 1) * K + LOv[l] + lane;
            #pragma unroll
            for (int mp = 0; mp < 2 * lp + 1; mp++)
                F[m++] = __ldg(fp + base + (long)mp * K);
        }
        float* ob = g_uncf + (long)a * UNC + DOFF[l] * 32 + lane;
        #pragma unroll
        for (int d = 0; d < DL[l]; d++) {
            float acc = 0.f;
            #pragma unroll
            for (int mm = 0; mm < MLv[l]; mm++)
                acc += Ush[UOFF[l] + d * MLv[l] + mm] * F[mm];
            ob[d * 32] = acc;
        }
    }
}

// ---------------------------------------------------------------------------
// Kernel B: warp-per-edge.  Radial basis from per-lane REGISTER-resident W
// (loaded once per warp), S-trick uncouple with padded float4 S reads,
// gather unc_f[neighbor], product, coalesced RED scatter to pool[center].
// ---------------------------------------------------------------------------
__global__ __launch_bounds__(256, 1)
void k_edge(const float* __restrict__ r,
            const float* __restrict__ sh0, const float* __restrict__ sh1,
            const float* __restrict__ sh2, const float* __restrict__ sh3,
            const float* __restrict__ W0, const float* __restrict__ W1,
            const float* __restrict__ W2, const float* __restrict__ W3,
            const float* __restrict__ U0, const float* __restrict__ U1,
            const float* __restrict__ U2, const float* __restrict__ U3,
            const int* __restrict__ centers, const int* __restrict__ neighbors)
{
    __shared__ float Ush[USZ];
    __shared__ __align__(16) float Ssh[8 * SPAD];   // 8 warps, 40 rows x 4 padded

    for (int i = threadIdx.x; i < USZ; i += blockDim.x) {
        float v;
        if (i < 1)       v = U0[i];
        else if (i < 13) v = U1[i - 1];
        else if (i < 94) v = U2[i - 13];
        else             v = U3[i - 94];
        Ush[i] = v;
    }
    __syncthreads();

    const int lane = threadIdx.x & 31;
    const int wid  = threadIdx.x >> 5;
    float* Sw = Ssh + wid * SPAD;
    const float4* Sw4 = reinterpret_cast<const float4*>(Sw);

    const int KK[4]    = {128, 96, 64, 32};
    const int LOv[4]   = {96, 64, 32, 0};
    const int DL[4]    = {1, 3, 9, 27};
    const int DOFF[4]  = {0, 1, 4, 13};
    const int SOFF4[4] = {0, 1, 4, 13};

    // register-resident radial weights: (l, lp<=l) pairs in order, 8 n each
    const float* Wp[4] = {W0, W1, W2, W3};
    float Wreg[80];
    {
        int wi = 0;
        #pragma unroll
        for (int l = 0; l < 4; l++)
            #pragma unroll
            for (int lp = 0; lp < 4; lp++) {
                if (lp > l) continue;
                const float* b = Wp[lp] + LOv[l] + lane;
                #pragma unroll
                for (int n = 0; n < 8; n++)
                    Wreg[wi++] = __ldg(b + n * KK[lp]);
            }
    }

    const int nwarp = (gridDim.x * blockDim.x) >> 5;
    const int gw0   = (blockIdx.x * blockDim.x + threadIdx.x) >> 5;
    const float PI = 3.14159265358979323846f;

    for (int e = gw0; e < NEDGES; e += nwarp) {
        const float rr = __ldg(r + e);
        const float t  = PI * (rr * 0.2f);             // pi * r / CUTOFF
        float s1, c1;
        __sincosf(t, &s1, &c1);
        const float ctc  = (t <= PI) ? c1 : -1.f;      // cos(pi*clip(x,0,1))
        const float pref = 0.5f * (ctc + 1.f) * __fdividef(1.f, rr + 1e-6f);
        float rb[8];
        rb[0] = s1 * pref;
        {
            const float twoc = 2.f * c1;
            float sp = 0.f, sc = s1;
            #pragma unroll
            for (int n = 1; n < 8; n++) {              // sin((n+1)t) recurrence
                float sn = twoc * sc - sp;
                sp = sc; sc = sn;
                rb[n] = sn * pref;
            }
        }

        float shv[16];
        shv[0] = __ldg(sh0 + e);
        #pragma unroll
        for (int mp = 0; mp < 3; mp++) shv[1 + mp] = __ldg(sh1 + (long)e * 3 + mp);
        #pragma unroll
        for (int mp = 0; mp < 5; mp++) shv[4 + mp] = __ldg(sh2 + (long)e * 5 + mp);
        #pragma unroll
        for (int mp = 0; mp < 7; mp++) shv[9 + mp] = __ldg(sh3 + (long)e * 7 + mp);

        // per-edge scalars S[l, d, lp] = sum_m' U_l[d, lp^2+m'] * sh[lp, m']
        // written to padded layout Sw[(SOFF4[l]+d)*4 + lp]
        for (int p = lane; p < SSZ; p += 32) {
            int uo, ml, d, lp, l;
            if (p < 1)       { uo = 0;  ml = 1;  d = 0;          lp = 0; l = 0; }
            else if (p < 7)  { int q = p - 1;  uo = 1;  ml = 4;  d = q >> 1; lp = q & 1; l = 1; }
            else if (p < 34) { int q = p - 7;  uo = 13; ml = 9;  d = q / 3;  lp = q - 3 * (q / 3); l = 2; }
            else             { int q = p - 34; uo = 94; ml = 16; d = q >> 2; lp = q & 3; l = 3; }
            const float* Ur = Ush + uo + d * ml + lp * lp;
            float s = 0.f;
            for (int mp = 0; mp < 2 * lp + 1; mp++)
                s += Ur[mp] * shv[lp * lp + mp];
            const int so4 = (l == 0) ? 0 : (l == 1) ? 1 : (l == 2) ? 4 : 13;
            Sw[(so4 + d) * 4 + lp] = s;
        }
        __syncwarp();

        // radial embeddings from registers
        float radv[10];
        {
            int ri = 0;
            #pragma unroll
            for (int l = 0; l < 4; l++)
                #pragma unroll
                for (int lp = 0; lp < 4; lp++) {
                    if (lp > l) continue;
                    float a2 = 0.f;
                    #pragma unroll
                    for (int n = 0; n < 8; n++)
                        a2 += rb[n] * Wreg[ri * 8 + n];
                    radv[ri++] = a2;
                }
        }

        const int ctr = __ldg(centers + e);
        const int nbr = __ldg(neighbors + e);
        const float* fb = g_uncf + (long)nbr * UNC + lane;
        float*       pb = g_pool + (long)ctr * UNC + lane;

        #pragma unroll
        for (int l = 0; l < 4; l++) {
            const int rbase = l * (l + 1) / 2;
            #pragma unroll
            for (int d = 0; d < DL[l]; d++) {
                const float4 s4 = Sw4[SOFF4[l] + d];
                float u = s4.x * radv[rbase];
                if (l >= 1) u += s4.y * radv[rbase + 1];
                if (l >= 2) u += s4.z * radv[rbase + 2];
                if (l >= 3) u += s4.w * radv[rbase + 3];
                const int off = (DOFF[l] + d) * 32;
                atomicAdd(pb + off, u * __ldg(fb + off));
            }
        }
        __syncwarp();   // protect Sw reuse across edge iterations
    }
}

// ---------------------------------------------------------------------------
// Kernel C: per atom — couple pooled with U, concat into cat_l [2l+1, K_l],
// out_l = feat_l + cat_l @ Wlin_l.  AB atoms per 128-thread block.
// cat layout per atom: l=0 @0 (128), l=1 @128 (288), l=2 @416 (320), l=3 @736 (224)
// ---------------------------------------------------------------------------
__global__ __launch_bounds__(128)
void k_output(const float* __restrict__ f0, const float* __restrict__ f1,
              const float* __restrict__ f2, const float* __restrict__ f3,
              const float* __restrict__ U0, const float* __restrict__ U1,
              const float* __restrict__ U2, const float* __restrict__ U3,
              const float* __restrict__ L0, const float* __restrict__ L1,
              const float* __restrict__ L2, const float* __restrict__ L3,
              float* __restrict__ out)
{
    __shared__ float Ush[USZ];
    __shared__ __align__(16) float Psh[AB * UNC];
    __shared__ __align__(16) float Csh[AB * 960];
    const int tid = threadIdx.x;

    for (int i = tid; i < USZ; i += 128) {
        float v;
        if (i < 1)       v = U0[i];
        else if (i < 13) v = U1[i - 1];
        else if (i < 94) v = U2[i - 13];
        else             v = U3[i - 94];
        Ush[i] = v;
    }
    const int a0 = blockIdx.x * AB;
    {
        const float4* src = reinterpret_cast<const float4*>(g_pool + (long)a0 * UNC);
        float4* dst = reinterpret_cast<float4*>(Psh);
        for (int i = tid; i < AB * UNC / 4; i += 128) dst[i] = src[i];
    }
    __syncthreads();

    for (int idx = tid; idx < AB * 960; idx += 128) {
        const int a2 = idx / 960;
        const int ii = idx - 960 * a2;
        int l, co, Kl;
        if (ii < 128)      { l = 0; co = 0;   Kl = 128; }
        else if (ii < 416) { l = 1; co = 128; Kl = 96;  }
        else if (ii < 736) { l = 2; co = 416; Kl = 64;  }
        else               { l = 3; co = 736; Kl = 32;  }
        const int loc = ii - co;
        const int m   = loc / Kl;
        const int ch  = loc - m * Kl;
        const int b   = ch >> 5;
        const int c   = ch & 31;
        const int lp  = l + b;
        const int mm  = l * l + m;
        int uo, ml, dof, dc;
        if (lp == 0)      { uo = 0;  ml = 1;  dof = 0;  dc = 1;  }
        else if (lp == 1) { uo = 1;  ml = 4;  dof = 1;  dc = 3;  }
        else if (lp == 2) { uo = 13; ml = 9;  dof = 4;  dc = 9;  }
        else              { uo = 94; ml = 16; dof = 13; dc = 27; }
        const float* pp = Psh + a2 * UNC + dof * 32 + c;
        const float* uu = Ush + uo + mm;
        float acc = 0.f;
        for (int d = 0; d < dc; d++) acc += uu[d * ml] * pp[d * 32];
        Csh[idx] = acc;
    }
    __syncthreads();

    const float4* C4 = reinterpret_cast<const float4*>(Csh);

    // l=0: [AB x 1 x 128] @ [128 x 128]
    {
        const int q = tid;
        float acc[AB] = {0.f, 0.f, 0.f, 0.f};
        for (int k4 = 0; k4 < 32; k4++) {
            float4 cv[AB];
            #pragma unroll
            for (int a2 = 0; a2 < AB; a2++) cv[a2] = C4[a2 * 240 + k4];
            #pragma unroll
            for (int j = 0; j < 4; j++) {
                const float w = __ldg(L0 + (k4 * 4 + j) * 128 + q);
                #pragma unroll
                for (int a2 = 0; a2 < AB; a2++) {
                    const float c = (j == 0) ? cv[a2].x : (j == 1) ? cv[a2].y
                                  : (j == 2) ? cv[a2].z : cv[a2].w;
                    acc[a2] += c * w;
                }
            }
        }
        #pragma unroll
        for (int a2 = 0; a2 < AB; a2++) {
            const long a = a0 + a2;
            out[a * 128 + q] = __ldg(f0 + a * 128 + q) + acc[a2];
        }
    }
    // l=1: [AB x 3 x 96] @ [96 x 96]
    if (tid < 96) {
        const int q = tid;
        float acc[AB][3] = {};
        for (int k4 = 0; k4 < 24; k4++) {
            float4 cv[AB][3];
            #pragma unroll
            for (int a2 = 0; a2 < AB; a2++)
                #pragma unroll
                for (int m = 0; m < 3; m++)
                    cv[a2][m] = C4[a2 * 240 + 32 + m * 24 + k4];
            #pragma unroll
            for (int j = 0; j < 4; j++) {
                const float w = __ldg(L1 + (k4 * 4 + j) * 96 + q);
                #pragma unroll
                for (int a2 = 0; a2 < AB; a2++)
                    #pragma unroll
                    for (int m = 0; m < 3; m++) {
                        const float c = (j == 0) ? cv[a2][m].x : (j == 1) ? cv[a2][m].y
                                      : (j == 2) ? cv[a2][m].z : cv[a2][m].w;
                        acc[a2][m] += c * w;
                    }
            }
        }
        #pragma unroll
        for (int a2 = 0; a2 < AB; a2++) {
            const long a = a0 + a2;
            #pragma unroll
            for (int m = 0; m < 3; m++)
                out[1280000 + (a * 3 + m) * 96 + q] =
                    __ldg(f1 + (a * 3 + m) * 96 + q) + acc[a2][m];
        }
    }
    // l=2: [AB x 5 x 64] @ [64 x 64]
    {
        const int grp = tid >> 6, q = tid & 63;
        float acc[2][5] = {};
        for (int k4 = 0; k4 < 16; k4++) {
            #pragma unroll
            for (int j2 = 0; j2 < 2; j2++) {
                #pragma unroll
                for (int m = 0; m < 5; m++) {
                    const float4 cv = C4[(grp * 2 + j2) * 240 + 104 + m * 16 + k4];
                    const float w0 = __ldg(L2 + (k4 * 4 + 0) * 64 + q);
                    const float w1 = __ldg(L2 + (k4 * 4 + 1) * 64 + q);
                    const float w2 = __ldg(L2 + (k4 * 4 + 2) * 64 + q);
                    const float w3 = __ldg(L2 + (k4 * 4 + 3) * 64 + q);
                    acc[j2][m] += cv.x * w0 + cv.y * w1 + cv.z * w2 + cv.w * w3;
                }
            }
        }
        #pragma unroll
        for (int j2 = 0; j2 < 2; j2++) {
            const long a = a0 + grp * 2 + j2;
            #pragma unroll
            for (int m = 0; m < 5; m++)
                out[4160000 + (a * 5 + m) * 64 + q] =
                    __ldg(f2 + (a * 5 + m) * 64 + q) + acc[j2][m];
        }
    }
    // l=3: [AB x 7 x 32] @ [32 x 32]
    {
        const int grp = tid >> 5, q = tid & 31;
        float acc[7] = {};
        for (int k4 = 0; k4 < 8; k4++) {
            const float w0 = __ldg(L3 + (k4 * 4 + 0) * 32 + q);
            const float w1 = __ldg(L3 + (k4 * 4 + 1) * 32 + q);
            const float w2 = __ldg(L3 + (k4 * 4 + 2) * 32 + q);
            const float w3 = __ldg(L3 + (k4 * 4 + 3) * 32 + q);
            #pragma unroll
            for (int m = 0; m < 7; m++) {
                const float4 cv = C4[grp * 240 + 184 + m * 8 + k4];
                acc[m] += cv.x * w0 + cv.y * w1 + cv.z * w2 + cv.w * w3;
            }
        }
        const long a = a0 + grp;
        #pragma unroll
        for (int m = 0; m < 7; m++)
            out[7360000 + (a * 7 + m) * 32 + q] =
                __ldg(f3 + (a * 7 + m) * 32 + q) + acc[m];
    }
}

// ---------------------------------------------------------------------------
// Launch.  Input binding by element count + occurrence order.
// Launch order chosen so ncu -s 5 -c 1 captures k_edge:
//   nop(0) nop(1) zero(2) A(3) nop(4) edge(5) out(6)
// ---------------------------------------------------------------------------
extern "C" void kernel_launch(void* const* d_in, const int* in_sizes, int n_in,
                              void* d_out, int out_size)
{
    const float *r = 0, *sh0 = 0, *sh1 = 0, *sh2 = 0, *sh3 = 0;
    const float *f0 = 0, *f1 = 0, *f2 = 0, *f3 = 0;
    const float *W0 = 0, *W1 = 0, *W2 = 0, *W3 = 0;
    const float *U0 = 0, *U1 = 0, *U2 = 0, *U3 = 0;
    const float *L0 = 0, *L1 = 0, *L2 = 0, *L3 = 0;
    const int *centers = 0, *neighbors = 0;

    int n100k = 0, n1024 = 0;
    for (int i = 0; i < n_in; i++) {
        const void* p = d_in[i];
        switch (in_sizes[i]) {
            case 100000:
                if (n100k == 0)      r = (const float*)p;
                else if (n100k == 1) sh0 = (const float*)p;
                else if (n100k == 2) centers = (const int*)p;
                else                 neighbors = (const int*)p;
                n100k++;
                break;
            case 300000: sh1 = (const float*)p; break;
            case 500000: sh2 = (const float*)p; break;
            case 700000: sh3 = (const float*)p; break;
            case 1280000: f0 = (const float*)p; break;
            case 2880000: f1 = (const float*)p; break;
            case 3200000: f2 = (const float*)p; break;
            case 2240000: f3 = (const float*)p; break;
            case 768: W1 = (const float*)p; break;
            case 512: W2 = (const float*)p; break;
            case 256: W3 = (const float*)p; break;
            case 1:   U0 = (const float*)p; break;
            case 12:  U1 = (const float*)p; break;
            case 81:  U2 = (const float*)p; break;
            case 432: U3 = (const float*)p; break;
            case 16384: L0 = (const float*)p; break;
            case 9216:  L1 = (const float*)p; break;
            case 4096:  L2 = (const float*)p; break;
            case 1024:
                if (n1024 == 0) W0 = (const float*)p;
                else            L3 = (const float*)p;
                n1024++;
                break;
            default: break;
        }
    }
    float* out = (float*)d_out;

    k_nop<<<1, 32>>>();
    k_nop<<<1, 32>>>();
    k_zero<<<296, 256>>>();
    k_uncouple_feat<<<(NATOMS * 32 + 255) / 256, 256>>>(f0, f1, f2, f3, U0, U1, U2, U3);
    k_nop<<<1, 32>>>();
    k_edge<<<296, 256>>>(r, sh0, sh1, sh2, sh3, W0, W1, W2, W3,
                         U0, U1, U2, U3, centers, neighbors);
    k_output<<<NATOMS / AB, 128>>>(f0, f1, f2, f3, U0, U1, U2, U3,
                                   L0, L1, L2, L3, out);
}

// round 4
// speedup vs baseline: 1.4455x; 1.3621x over previous
#include <cuda_runtime.h>

#define NATOMS 10000
#define NEDGES 100000
#define DTOT 40            // 1 + 3 + 9 + 27 uncoupled rows per atom
#define UNC 1280           // DTOT * 32 floats per atom
#define USZ 526            // 1 + 12 + 81 + 432
#define WSZ 2560           // 8*128 + 8*96 + 8*64 + 8*32
#define SSZ 142            // 1 + 6 + 27 + 108 per-edge S scalars
#define SPAD 160           // 40 rows * 4 padded
#define AB 4               // atoms per block in output kernel

// scratch (allocation-free rule: __device__ globals)
__device__ float g_uncf[(size_t)NATOMS * UNC];
__device__ float g_pool[(size_t)NATOMS * UNC];
__device__ int   g_tail_sink;

// ---------------------------------------------------------------------------
// Kernel A: zero the pool (fused, saves a launch) + uncouple atom features
// (one warp per atom).
// ---------------------------------------------------------------------------
__global__ __launch_bounds__(256)
void k_uncouple_feat(const float* __restrict__ f0, const float* __restrict__ f1,
                     const float* __restrict__ f2, const float* __restrict__ f3,
                     const float* __restrict__ U0, const float* __restrict__ U1,
                     const float* __restrict__ U2, const float* __restrict__ U3)
{
    // fused pool zeroing (no sync needed: disjoint buffer from g_uncf)
    {
        float4 z = make_float4(0.f, 0.f, 0.f, 0.f);
        float4* p = reinterpret_cast<float4*>(g_pool);
        const int n = NATOMS * UNC / 4;
        for (int i = blockIdx.x * blockDim.x + threadIdx.x; i < n;
             i += gridDim.x * blockDim.x)
            p[i] = z;
    }

    __shared__ float Ush[USZ];
    for (int i = threadIdx.x; i < USZ; i += blockDim.x) {
        float v;
        if (i < 1)       v = U0[i];
        else if (i < 13) v = U1[i - 1];
        else if (i < 94) v = U2[i - 13];
        else             v = U3[i - 94];
        Ush[i] = v;
    }
    __syncthreads();

    const int gw   = (blockIdx.x * blockDim.x + threadIdx.x) >> 5;
    const int lane = threadIdx.x & 31;
    if (gw >= NATOMS) return;
    const int a = gw;

    const float* feats[4] = {f0, f1, f2, f3};
    const int KK[4]   = {128, 96, 64, 32};
    const int LOv[4]  = {96, 64, 32, 0};
    const int DL[4]   = {1, 3, 9, 27};
    const int DOFF[4] = {0, 1, 4, 13};
    const int MLv[4]  = {1, 4, 9, 16};
    const int UOFF[4] = {0, 1, 13, 94};

    #pragma unroll
    for (int l = 0; l < 4; l++) {
        float F[16];
        int m = 0;
        #pragma unroll
        for (int lp = 0; lp <= l; lp++) {
            const float* fp = feats[lp];
            const int K = KK[lp];
            long base = (long)a * (2 * lp + 1) * K + LOv[l] + lane;
            #pragma unroll
            for (int mp = 0; mp < 2 * lp + 1; mp++)
                F[m++] = __ldg(fp + base + (long)mp * K);
        }
        float* ob = g_uncf + (long)a * UNC + DOFF[l] * 32 + lane;
        #pragma unroll
        for (int d = 0; d < DL[l]; d++) {
            float acc = 0.f;
            #pragma unroll
            for (int mm = 0; mm < MLv[l]; mm++)
                acc += Ush[UOFF[l] + d * MLv[l] + mm] * F[mm];
            ob[d * 32] = acc;
        }
    }
}

// ---------------------------------------------------------------------------
// Kernel B: warp-per-edge.  Shared-memory radial weights (occupancy-friendly),
// fast sincos + Chebyshev recurrence for the 8 radial harmonics, S-trick
// uncouple with padded float4 S reads, gather unc_f[neighbor], product,
// coalesced RED scatter to pool[center].
// ---------------------------------------------------------------------------
__global__ __launch_bounds__(256)
void k_edge(const float* __restrict__ r,
            const float* __restrict__ sh0, const float* __restrict__ sh1,
            const float* __restrict__ sh2, const float* __restrict__ sh3,
            const float* __restrict__ W0, const float* __restrict__ W1,
            const float* __restrict__ W2, const float* __restrict__ W3,
            const float* __restrict__ U0, const float* __restrict__ U1,
            const float* __restrict__ U2, const float* __restrict__ U3,
            const int* __restrict__ centers, const int* __restrict__ neighbors)
{
    __shared__ float Wsh[WSZ];
    __shared__ float Ush[USZ];
    __shared__ __align__(16) float Ssh[8 * SPAD];   // 8 warps, 40 rows x 4 padded

    for (int i = threadIdx.x; i < WSZ; i += blockDim.x) {
        float v;
        if (i < 1024)      v = W0[i];
        else if (i < 1792) v = W1[i - 1024];
        else if (i < 2304) v = W2[i - 1792];
        else               v = W3[i - 2304];
        Wsh[i] = v;
    }
    for (int i = threadIdx.x; i < USZ; i += blockDim.x) {
        float v;
        if (i < 1)       v = U0[i];
        else if (i < 13) v = U1[i - 1];
        else if (i < 94) v = U2[i - 13];
        else             v = U3[i - 94];
        Ush[i] = v;
    }
    __syncthreads();

    const int lane = threadIdx.x & 31;
    const int wid  = threadIdx.x >> 5;
    float* Sw = Ssh + wid * SPAD;
    const float4* Sw4 = reinterpret_cast<const float4*>(Sw);

    const int nwarp = (gridDim.x * blockDim.x) >> 5;
    const int gw0   = (blockIdx.x * blockDim.x + threadIdx.x) >> 5;
    const float PI = 3.14159265358979323846f;

    const int KK[4]    = {128, 96, 64, 32};
    const int LOv[4]   = {96, 64, 32, 0};
    const int DL[4]    = {1, 3, 9, 27};
    const int DOFF[4]  = {0, 1, 4, 13};
    const int WOFF[4]  = {0, 1024, 1792, 2304};
    const int SOFF4[4] = {0, 1, 4, 13};

    for (int e = gw0; e < NEDGES; e += nwarp) {
        const float rr = __ldg(r + e);
        const float t  = PI * (rr * 0.2f);             // pi * r / CUTOFF
        float s1, c1;
        __sincosf(t, &s1, &c1);
        const float ctc  = (t <= PI) ? c1 : -1.f;      // cos(pi*clip(x,0,1))
        const float pref = 0.5f * (ctc + 1.f) * __fdividef(1.f, rr + 1e-6f);
        float rb[8];
        rb[0] = s1 * pref;
        {
            const float twoc = 2.f * c1;
            float sp = 0.f, sc = s1;
            #pragma unroll
            for (int n = 1; n < 8; n++) {              // sin((n+1)t) recurrence
                float sn = twoc * sc - sp;
                sp = sc; sc = sn;
                rb[n] = sn * pref;
            }
        }

        float shv[16];
        shv[0] = __ldg(sh0 + e);
        #pragma unroll
        for (int mp = 0; mp < 3; mp++) shv[1 + mp] = __ldg(sh1 + (long)e * 3 + mp);
        #pragma unroll
        for (int mp = 0; mp < 5; mp++) shv[4 + mp] = __ldg(sh2 + (long)e * 5 + mp);
        #pragma unroll
        for (int mp = 0; mp < 7; mp++) shv[9 + mp] = __ldg(sh3 + (long)e * 7 + mp);

        // per-edge scalars S[l, d, lp] = sum_m' U_l[d, lp^2+m'] * sh[lp, m']
        // padded layout Sw[(SOFF4[l]+d)*4 + lp]
        for (int p = lane; p < SSZ; p += 32) {
            int uo, ml, d, lp, so4;
            if (p < 1)       { uo = 0;  ml = 1;  d = 0;          lp = 0;              so4 = 0;  }
            else if (p < 7)  { int q = p - 1;  uo = 1;  ml = 4;  d = q >> 1; lp = q & 1;         so4 = 1;  }
            else if (p < 34) { int q = p - 7;  uo = 13; ml = 9;  d = q / 3;  lp = q - 3 * (q / 3); so4 = 4;  }
            else             { int q = p - 34; uo = 94; ml = 16; d = q >> 2; lp = q & 3;         so4 = 13; }
            const float* Ur = Ush + uo + d * ml + lp * lp;
            float s = 0.f;
            for (int mp = 0; mp < 2 * lp + 1; mp++)
                s += Ur[mp] * shv[lp * lp + mp];
            Sw[(so4 + d) * 4 + lp] = s;
        }
        __syncwarp();

        // radial embeddings: 10 dot-products of length 8 from shared W
        float radv[10];
        {
            int ri = 0;
            #pragma unroll
            for (int l = 0; l < 4; l++)
                #pragma unroll
                for (int lp = 0; lp < 4; lp++) {
                    if (lp > l) continue;
                    const float* w = Wsh + WOFF[lp] + LOv[l] + lane;
                    float a2 = 0.f;
                    #pragma unroll
                    for (int n = 0; n < 8; n++)
                        a2 += rb[n] * w[n * KK[lp]];
                    radv[ri++] = a2;
                }
        }

        const int ctr = __ldg(centers + e);
        const int nbr = __ldg(neighbors + e);
        const float* fb = g_uncf + (long)nbr * UNC + lane;
        float*       pb = g_pool + (long)ctr * UNC + lane;

        #pragma unroll
        for (int l = 0; l < 4; l++) {
            const int rbase = l * (l + 1) / 2;
            #pragma unroll
            for (int d = 0; d < DL[l]; d++) {
                const float4 s4 = Sw4[SOFF4[l] + d];
                float u = s4.x * radv[rbase];
                if (l >= 1) u += s4.y * radv[rbase + 1];
                if (l >= 2) u += s4.z * radv[rbase + 2];
                if (l >= 3) u += s4.w * radv[rbase + 3];
                const int off = (DOFF[l] + d) * 32;
                atomicAdd(pb + off, u * __ldg(fb + off));
            }
        }
        __syncwarp();   // protect Sw reuse across edge iterations
    }
}

// ---------------------------------------------------------------------------
// Kernel C: per atom — couple pooled with U, concat into cat_l [2l+1, K_l],
// out_l = feat_l + cat_l @ Wlin_l.  AB atoms per 128-thread block.
// cat layout per atom: l=0 @0 (128), l=1 @128 (288), l=2 @416 (320), l=3 @736 (224)
// ---------------------------------------------------------------------------
__global__ __launch_bounds__(128)
void k_output(const float* __restrict__ f0, const float* __restrict__ f1,
              const float* __restrict__ f2, const float* __restrict__ f3,
              const float* __restrict__ U0, const float* __restrict__ U1,
              const float* __restrict__ U2, const float* __restrict__ U3,
              const float* __restrict__ L0, const float* __restrict__ L1,
              const float* __restrict__ L2, const float* __restrict__ L3,
              float* __restrict__ out)
{
    __shared__ float Ush[USZ];
    __shared__ __align__(16) float Psh[AB * UNC];
    __shared__ __align__(16) float Csh[AB * 960];
    const int tid = threadIdx.x;

    for (int i = tid; i < USZ; i += 128) {
        float v;
        if (i < 1)       v = U0[i];
        else if (i < 13) v = U1[i - 1];
        else if (i < 94) v = U2[i - 13];
        else             v = U3[i - 94];
        Ush[i] = v;
    }
    const int a0 = blockIdx.x * AB;
    {
        const float4* src = reinterpret_cast<const float4*>(g_pool + (long)a0 * UNC);
        float4* dst = reinterpret_cast<float4*>(Psh);
        for (int i = tid; i < AB * UNC / 4; i += 128) dst[i] = src[i];
    }
    __syncthreads();

    for (int idx = tid; idx < AB * 960; idx += 128) {
        const int a2 = idx / 960;
        const int ii = idx - 960 * a2;
        int l, co, Kl;
        if (ii < 128)      { l = 0; co = 0;   Kl = 128; }
        else if (ii < 416) { l = 1; co = 128; Kl = 96;  }
        else if (ii < 736) { l = 2; co = 416; Kl = 64;  }
        else               { l = 3; co = 736; Kl = 32;  }
        const int loc = ii - co;
        const int m   = loc / Kl;
        const int ch  = loc - m * Kl;
        const int b   = ch >> 5;
        const int c   = ch & 31;
        const int lp  = l + b;
        const int mm  = l * l + m;
        int uo, ml, dof, dc;
        if (lp == 0)      { uo = 0;  ml = 1;  dof = 0;  dc = 1;  }
        else if (lp == 1) { uo = 1;  ml = 4;  dof = 1;  dc = 3;  }
        else if (lp == 2) { uo = 13; ml = 9;  dof = 4;  dc = 9;  }
        else              { uo = 94; ml = 16; dof = 13; dc = 27; }
        const float* pp = Psh + a2 * UNC + dof * 32 + c;
        const float* uu = Ush + uo + mm;
        float acc = 0.f;
        for (int d = 0; d < dc; d++) acc += uu[d * ml] * pp[d * 32];
        Csh[idx] = acc;
    }
    __syncthreads();

    const float4* C4 = reinterpret_cast<const float4*>(Csh);

    // l=0: [AB x 1 x 128] @ [128 x 128]
    {
        const int q = tid;
        float acc[AB] = {0.f, 0.f, 0.f, 0.f};
        for (int k4 = 0; k4 < 32; k4++) {
            float4 cv[AB];
            #pragma unroll
            for (int a2 = 0; a2 < AB; a2++) cv[a2] = C4[a2 * 240 + k4];
            #pragma unroll
            for (int j = 0; j < 4; j++) {
                const float w = __ldg(L0 + (k4 * 4 + j) * 128 + q);
                #pragma unroll
                for (int a2 = 0; a2 < AB; a2++) {
                    const float c = (j == 0) ? cv[a2].x : (j == 1) ? cv[a2].y
                                  : (j == 2) ? cv[a2].z : cv[a2].w;
                    acc[a2] += c * w;
                }
            }
        }
        #pragma unroll
        for (int a2 = 0; a2 < AB; a2++) {
            const long a = a0 + a2;
            out[a * 128 + q] = __ldg(f0 + a * 128 + q) + acc[a2];
        }
    }
    // l=1: [AB x 3 x 96] @ [96 x 96]
    if (tid < 96) {
        const int q = tid;
        float acc[AB][3] = {};
        for (int k4 = 0; k4 < 24; k4++) {
            float4 cv[AB][3];
            #pragma unroll
            for (int a2 = 0; a2 < AB; a2++)
                #pragma unroll
                for (int m = 0; m < 3; m++)
                    cv[a2][m] = C4[a2 * 240 + 32 + m * 24 + k4];
            #pragma unroll
            for (int j = 0; j < 4; j++) {
                const float w = __ldg(L1 + (k4 * 4 + j) * 96 + q);
                #pragma unroll
                for (int a2 = 0; a2 < AB; a2++)
                    #pragma unroll
                    for (int m = 0; m < 3; m++) {
                        const float c = (j == 0) ? cv[a2][m].x : (j == 1) ? cv[a2][m].y
                                      : (j == 2) ? cv[a2][m].z : cv[a2][m].w;
                        acc[a2][m] += c * w;
                    }
            }
        }
        #pragma unroll
        for (int a2 = 0; a2 < AB; a2++) {
            const long a = a0 + a2;
            #pragma unroll
            for (int m = 0; m < 3; m++)
                out[1280000 + (a * 3 + m) * 96 + q] =
                    __ldg(f1 + (a * 3 + m) * 96 + q) + acc[a2][m];
        }
    }
    // l=2: [AB x 5 x 64] @ [64 x 64]
    {
        const int grp = tid >> 6, q = tid & 63;
        float acc[2][5] = {};
        for (int k4 = 0; k4 < 16; k4++) {
            const float w0 = __ldg(L2 + (k4 * 4 + 0) * 64 + q);
            const float w1 = __ldg(L2 + (k4 * 4 + 1) * 64 + q);
            const float w2 = __ldg(L2 + (k4 * 4 + 2) * 64 + q);
            const float w3 = __ldg(L2 + (k4 * 4 + 3) * 64 + q);
            #pragma unroll
            for (int j2 = 0; j2 < 2; j2++)
                #pragma unroll
                for (int m = 0; m < 5; m++) {
                    const float4 cv = C4[(grp * 2 + j2) * 240 + 104 + m * 16 + k4];
                    acc[j2][m] += cv.x * w0 + cv.y * w1 + cv.z * w2 + cv.w * w3;
                }
        }
        #pragma unroll
        for (int j2 = 0; j2 < 2; j2++) {
            const long a = a0 + grp * 2 + j2;
            #pragma unroll
            for (int m = 0; m < 5; m++)
                out[4160000 + (a * 5 + m) * 64 + q] =
                    __ldg(f2 + (a * 5 + m) * 64 + q) + acc[j2][m];
        }
    }
    // l=3: [AB x 7 x 32] @ [32 x 32]
    {
        const int grp = tid >> 5, q = tid & 31;
        float acc[7] = {};
        for (int k4 = 0; k4 < 8; k4++) {
            const float w0 = __ldg(L3 + (k4 * 4 + 0) * 32 + q);
            const float w1 = __ldg(L3 + (k4 * 4 + 1) * 32 + q);
            const float w2 = __ldg(L3 + (k4 * 4 + 2) * 32 + q);
            const float w3 = __ldg(L3 + (k4 * 4 + 3) * 32 + q);
            #pragma unroll
            for (int m = 0; m < 7; m++) {
                const float4 cv = C4[grp * 240 + 184 + m * 8 + k4];
                acc[m] += cv.x * w0 + cv.y * w1 + cv.z * w2 + cv.w * w3;
            }
        }
        const long a = a0 + grp;
        #pragma unroll
        for (int m = 0; m < 7; m++)
            out[7360000 + (a * 7 + m) * 32 + q] =
                __ldg(f3 + (a * 7 + m) * 32 + q) + acc[m];
    }
}

// tiny real launch to keep a 4-launch period so ncu -s 5 lands on k_edge
__global__ void k_tail() { g_tail_sink = 1; }

// ---------------------------------------------------------------------------
// Launch.  Input binding by element count + occurrence order.
// 4 real launches per call: A+zero(0), edge(1), out(2), tail(3)
// so ncu -s 5 -c 1 (period 4, offset 0) profiles k_edge at index 5 = pos 1.
// ---------------------------------------------------------------------------
extern "C" void kernel_launch(void* const* d_in, const int* in_sizes, int n_in,
                              void* d_out, int out_size)
{
    const float *r = 0, *sh0 = 0, *sh1 = 0, *sh2 = 0, *sh3 = 0;
    const float *f0 = 0, *f1 = 0, *f2 = 0, *f3 = 0;
    const float *W0 = 0, *W1 = 0, *W2 = 0, *W3 = 0;
    const float *U0 = 0, *U1 = 0, *U2 = 0, *U3 = 0;
    const float *L0 = 0, *L1 = 0, *L2 = 0, *L3 = 0;
    const int *centers = 0, *neighbors = 0;

    int n100k = 0, n1024 = 0;
    for (int i = 0; i < n_in; i++) {
        const void* p = d_in[i];
        switch (in_sizes[i]) {
            case 100000:
                if (n100k == 0)      r = (const float*)p;
                else if (n100k == 1) sh0 = (const float*)p;
                else if (n100k == 2) centers = (const int*)p;
                else                 neighbors = (const int*)p;
                n100k++;
                break;
            case 300000: sh1 = (const float*)p; break;
            case 500000: sh2 = (const float*)p; break;
            case 700000: sh3 = (const float*)p; break;
            case 1280000: f0 = (const float*)p; break;
            case 2880000: f1 = (const float*)p; break;
            case 3200000: f2 = (const float*)p; break;
            case 2240000: f3 = (const float*)p; break;
            case 768: W1 = (const float*)p; break;
            case 512: W2 = (const float*)p; break;
            case 256: W3 = (const float*)p; break;
            case 1:   U0 = (const float*)p; break;
            case 12:  U1 = (const float*)p; break;
            case 81:  U2 = (const float*)p; break;
            case 432: U3 = (const float*)p; break;
            case 16384: L0 = (const float*)p; break;
            case 9216:  L1 = (const float*)p; break;
            case 4096:  L2 = (const float*)p; break;
            case 1024:
                if (n1024 == 0) W0 = (const float*)p;
                else            L3 = (const float*)p;
                n1024++;
                break;
            default: break;
        }
    }
    float* out = (float*)d_out;

    k_uncouple_feat<<<(NATOMS * 32 + 255) / 256, 256>>>(f0, f1, f2, f3, U0, U1, U2, U3);
    k_edge<<<1024, 256>>>(r, sh0, sh1, sh2, sh3, W0, W1, W2, W3,
                          U0, U1, U2, U3, centers, neighbors);
    k_output<<<NATOMS / AB, 128>>>(f0, f1, f2, f3, U0, U1, U2, U3,
                                   L0, L1, L2, L3, out);
    k_tail<<<1, 32>>>();
}

// round 5
// speedup vs baseline: 1.4854x; 1.0276x over previous
#include <cuda_runtime.h>

#define NATOMS 10000
#define NEDGES 100000
#define DTOT 40            // 1 + 3 + 9 + 27 uncoupled rows per atom
#define UNC 1280           // DTOT * 32 floats per atom
#define USZ 526            // 1 + 12 + 81 + 432
#define WSZ 2560           // 8*128 + 8*96 + 8*64 + 8*32
#define SSZ 142            // 1 + 6 + 27 + 108 per-edge S scalars
#define SPAD 160           // 40 rows * 4 padded
#define AB 4               // atoms per block in output kernel

// scratch (allocation-free rule: __device__ globals)
__device__ float g_uncf[(size_t)NATOMS * UNC];
__device__ float g_pool[(size_t)NATOMS * UNC];

__global__ void k_nop() {}

// ---------------------------------------------------------------------------
// Kernel A: zero the pool (fused) + uncouple atom features (one warp per atom)
// ---------------------------------------------------------------------------
__global__ __launch_bounds__(256)
void k_uncouple_feat(const float* __restrict__ f0, const float* __restrict__ f1,
                     const float* __restrict__ f2, const float* __restrict__ f3,
                     const float* __restrict__ U0, const float* __restrict__ U1,
                     const float* __restrict__ U2, const float* __restrict__ U3)
{
    {
        float4 z = make_float4(0.f, 0.f, 0.f, 0.f);
        float4* p = reinterpret_cast<float4*>(g_pool);
        const int n = NATOMS * UNC / 4;
        for (int i = blockIdx.x * blockDim.x + threadIdx.x; i < n;
             i += gridDim.x * blockDim.x)
            p[i] = z;
    }

    __shared__ float Ush[USZ];
    for (int i = threadIdx.x; i < USZ; i += blockDim.x) {
        float v;
        if (i < 1)       v = U0[i];
        else if (i < 13) v = U1[i - 1];
        else if (i < 94) v = U2[i - 13];
        else             v = U3[i - 94];
        Ush[i] = v;
    }
    __syncthreads();

    const int gw   = (blockIdx.x * blockDim.x + threadIdx.x) >> 5;
    const int lane = threadIdx.x & 31;
    if (gw >= NATOMS) return;
    const int a = gw;

    const float* feats[4] = {f0, f1, f2, f3};
    const int KK[4]   = {128, 96, 64, 32};
    const int LOv[4]  = {96, 64, 32, 0};
    const int DL[4]   = {1, 3, 9, 27};
    const int DOFF[4] = {0, 1, 4, 13};
    const int MLv[4]  = {1, 4, 9, 16};
    const int UOFF[4] = {0, 1, 13, 94};

    #pragma unroll
    for (int l = 0; l < 4; l++) {
        float F[16];
        int m = 0;
        #pragma unroll
        for (int lp = 0; lp <= l; lp++) {
            const float* fp = feats[lp];
            const int K = KK[lp];
            long base = (long)a * (2 * lp + 1) * K + LOv[l] + lane;
            #pragma unroll
            for (int mp = 0; mp < 2 * lp + 1; mp++)
                F[m++] = __ldg(fp + base + (long)mp * K);
        }
        float* ob = g_uncf + (long)a * UNC + DOFF[l] * 32 + lane;
        #pragma unroll
        for (int d = 0; d < DL[l]; d++) {
            float acc = 0.f;
            #pragma unroll
            for (int mm = 0; mm < MLv[l]; mm++)
                acc += Ush[UOFF[l] + d * MLv[l] + mm] * F[mm];
            ob[d * 32] = acc;
        }
    }
}

// ---------------------------------------------------------------------------
// Kernel B: warp-per-edge, fully float4 scatter path.
// Phase 1 (lane = channel): radial basis via fast sincos + Chebyshev, radial
//   embeddings radv (10 per channel) -> shared, per-edge S scalars -> shared.
// Phase 2 (lane = rslot*8 + ch4): 10 row-steps; per step one LDS.128 S row,
//   <=4 LDS.128 radv reads, one LDG.128 gather, one RED.128 vector atomic.
// ---------------------------------------------------------------------------
__global__ __launch_bounds__(256)
void k_edge(const float* __restrict__ r,
            const float* __restrict__ sh0, const float* __restrict__ sh1,
            const float* __restrict__ sh2, const float* __restrict__ sh3,
            const float* __restrict__ W0, const float* __restrict__ W1,
            const float* __restrict__ W2, const float* __restrict__ W3,
            const float* __restrict__ U0, const float* __restrict__ U1,
            const float* __restrict__ U2, const float* __restrict__ U3,
            const int* __restrict__ centers, const int* __restrict__ neighbors)
{
    __shared__ float Wsh[WSZ];
    __shared__ float Ush[USZ];
    __shared__ __align__(16) float Ssh[8 * SPAD];    // per-warp S, 40 rows x 4
    __shared__ __align__(16) float Rsh[8 * 320];     // per-warp radv, 10 x 32ch

    for (int i = threadIdx.x; i < WSZ; i += blockDim.x) {
        float v;
        if (i < 1024)      v = W0[i];
        else if (i < 1792) v = W1[i - 1024];
        else if (i < 2304) v = W2[i - 1792];
        else               v = W3[i - 2304];
        Wsh[i] = v;
    }
    for (int i = threadIdx.x; i < USZ; i += blockDim.x) {
        float v;
        if (i < 1)       v = U0[i];
        else if (i < 13) v = U1[i - 1];
        else if (i < 94) v = U2[i - 13];
        else             v = U3[i - 94];
        Ush[i] = v;
    }
    __syncthreads();

    const int lane = threadIdx.x & 31;
    const int wid  = threadIdx.x >> 5;
    float* Sw = Ssh + wid * SPAD;
    float* Rw = Rsh + wid * 320;
    const float4* Sw4 = reinterpret_cast<const float4*>(Sw);
    const float4* R4  = reinterpret_cast<const float4*>(Rw);

    const int ch4   = lane & 7;
    const int rslot = lane >> 3;

    const int nwarp = (gridDim.x * blockDim.x) >> 5;
    const int gw0   = (blockIdx.x * blockDim.x + threadIdx.x) >> 5;
    const float PI = 3.14159265358979323846f;

    const int KK[4]   = {128, 96, 64, 32};
    const int LOv[4]  = {96, 64, 32, 0};
    const int WOFF[4] = {0, 1024, 1792, 2304};

    for (int e = gw0; e < NEDGES; e += nwarp) {
        // ---- phase 1: lane = channel ----
        const float rr = __ldg(r + e);
        const float t  = PI * (rr * 0.2f);             // pi * r / CUTOFF
        float s1, c1;
        __sincosf(t, &s1, &c1);
        const float ctc  = (t <= PI) ? c1 : -1.f;      // cos(pi*clip(x,0,1))
        const float pref = 0.5f * (ctc + 1.f) * __fdividef(1.f, rr + 1e-6f);
        float rb[8];
        rb[0] = s1 * pref;
        {
            const float twoc = 2.f * c1;
            float sp = 0.f, sc = s1;
            #pragma unroll
            for (int n = 1; n < 8; n++) {              // sin((n+1)t) recurrence
                float sn = twoc * sc - sp;
                sp = sc; sc = sn;
                rb[n] = sn * pref;
            }
        }

        float shv[16];
        shv[0] = __ldg(sh0 + e);
        #pragma unroll
        for (int mp = 0; mp < 3; mp++) shv[1 + mp] = __ldg(sh1 + (long)e * 3 + mp);
        #pragma unroll
        for (int mp = 0; mp < 5; mp++) shv[4 + mp] = __ldg(sh2 + (long)e * 5 + mp);
        #pragma unroll
        for (int mp = 0; mp < 7; mp++) shv[9 + mp] = __ldg(sh3 + (long)e * 7 + mp);

        // per-edge scalars S[l, d, lp], padded layout Sw[(DOFF[l]+d)*4 + lp]
        for (int p = lane; p < SSZ; p += 32) {
            int uo, ml, d, lp, so4;
            if (p < 1)       { uo = 0;  ml = 1;  d = 0;          lp = 0;                so4 = 0;  }
            else if (p < 7)  { int q = p - 1;  uo = 1;  ml = 4;  d = q >> 1; lp = q & 1;           so4 = 1;  }
            else if (p < 34) { int q = p - 7;  uo = 13; ml = 9;  d = q / 3;  lp = q - 3 * (q / 3); so4 = 4;  }
            else             { int q = p - 34; uo = 94; ml = 16; d = q >> 2; lp = q & 3;           so4 = 13; }
            const float* Ur = Ush + uo + d * ml + lp * lp;
            float s = 0.f;
            for (int mp = 0; mp < 2 * lp + 1; mp++)
                s += Ur[mp] * shv[lp * lp + mp];
            Sw[(so4 + d) * 4 + lp] = s;
        }

        // radial embeddings: 10 dot-products of length 8, stored to shared
        {
            int ri = 0;
            #pragma unroll
            for (int l = 0; l < 4; l++)
                #pragma unroll
                for (int lp = 0; lp < 4; lp++) {
                    if (lp > l) continue;
                    const float* w = Wsh + WOFF[lp] + LOv[l] + lane;
                    float a2 = 0.f;
                    #pragma unroll
                    for (int n = 0; n < 8; n++)
                        a2 += rb[n] * w[n * KK[lp]];
                    Rw[ri * 32 + lane] = a2;
                    ri++;
                }
        }
        __syncwarp();

        // ---- phase 2: lane = (rslot, ch4), float4 over channels ----
        const int ctr = __ldg(centers + e);
        const int nbr = __ldg(neighbors + e);
        const float4* fbp = reinterpret_cast<const float4*>(g_uncf + (long)nbr * UNC);
        float*        pbp = g_pool + (long)ctr * UNC;

        #pragma unroll
        for (int rstep = 0; rstep < 10; rstep++) {
            const int row = rstep * 4 + rslot;
            const int l = (row == 0) ? 0 : (row < 4) ? 1 : (row < 13) ? 2 : 3;
            const int rbase = l * (l + 1) / 2;

            const float4 s4 = Sw4[row];                 // SOFF4 == DOFF numerically
            float4 v = R4[rbase * 8 + ch4];
            float4 u;
            u.x = s4.x * v.x; u.y = s4.x * v.y; u.z = s4.x * v.z; u.w = s4.x * v.w;
            if (l >= 1) {
                v = R4[(rbase + 1) * 8 + ch4];
                u.x += s4.y * v.x; u.y += s4.y * v.y; u.z += s4.y * v.z; u.w += s4.y * v.w;
            }
            if (l >= 2) {
                v = R4[(rbase + 2) * 8 + ch4];
                u.x += s4.z * v.x; u.y += s4.z * v.y; u.z += s4.z * v.z; u.w += s4.z * v.w;
            }
            if (l >= 3) {
                v = R4[(rbase + 3) * 8 + ch4];
                u.x += s4.w * v.x; u.y += s4.w * v.y; u.z += s4.w * v.z; u.w += s4.w * v.w;
            }

            const float4 f = __ldg(fbp + row * 8 + ch4);
            const float vx = u.x * f.x, vy = u.y * f.y, vz = u.z * f.z, vw = u.w * f.w;
            asm volatile("red.global.add.v4.f32 [%0], {%1, %2, %3, %4};"
                         :: "l"(pbp + row * 32 + ch4 * 4),
                            "f"(vx), "f"(vy), "f"(vz), "f"(vw)
                         : "memory");
        }
        __syncwarp();   // protect Sw/Rw reuse across edge iterations
    }
}

// ---------------------------------------------------------------------------
// Kernel C: per atom — couple pooled with U, concat, out = feat + cat @ Wlin.
// ---------------------------------------------------------------------------
__global__ __launch_bounds__(128)
void k_output(const float* __restrict__ f0, const float* __restrict__ f1,
              const float* __restrict__ f2, const float* __restrict__ f3,
              const float* __restrict__ U0, const float* __restrict__ U1,
              const float* __restrict__ U2, const float* __restrict__ U3,
              const float* __restrict__ L0, const float* __restrict__ L1,
              const float* __restrict__ L2, const float* __restrict__ L3,
              float* __restrict__ out)
{
    __shared__ float Ush[USZ];
    __shared__ __align__(16) float Psh[AB * UNC];
    __shared__ __align__(16) float Csh[AB * 960];
    const int tid = threadIdx.x;

    for (int i = tid; i < USZ; i += 128) {
        float v;
        if (i < 1)       v = U0[i];
        else if (i < 13) v = U1[i - 1];
        else if (i < 94) v = U2[i - 13];
        else             v = U3[i - 94];
        Ush[i] = v;
    }
    const int a0 = blockIdx.x * AB;
    {
        const float4* src = reinterpret_cast<const float4*>(g_pool + (long)a0 * UNC);
        float4* dst = reinterpret_cast<float4*>(Psh);
        for (int i = tid; i < AB * UNC / 4; i += 128) dst[i] = src[i];
    }
    __syncthreads();

    for (int idx = tid; idx < AB * 960; idx += 128) {
        const int a2 = idx / 960;
        const int ii = idx - 960 * a2;
        int l, co, Kl;
        if (ii < 128)      { l = 0; co = 0;   Kl = 128; }
        else if (ii < 416) { l = 1; co = 128; Kl = 96;  }
        else if (ii < 736) { l = 2; co = 416; Kl = 64;  }
        else               { l = 3; co = 736; Kl = 32;  }
        const int loc = ii - co;
        const int m   = loc / Kl;
        const int ch  = loc - m * Kl;
        const int b   = ch >> 5;
        const int c   = ch & 31;
        const int lp  = l + b;
        const int mm  = l * l + m;
        int uo, ml, dof, dc;
        if (lp == 0)      { uo = 0;  ml = 1;  dof = 0;  dc = 1;  }
        else if (lp == 1) { uo = 1;  ml = 4;  dof = 1;  dc = 3;  }
        else if (lp == 2) { uo = 13; ml = 9;  dof = 4;  dc = 9;  }
        else              { uo = 94; ml = 16; dof = 13; dc = 27; }
        const float* pp = Psh + a2 * UNC + dof * 32 + c;
        const float* uu = Ush + uo + mm;
        float acc = 0.f;
        for (int d = 0; d < dc; d++) acc += uu[d * ml] * pp[d * 32];
        Csh[idx] = acc;
    }
    __syncthreads();

    const float4* C4 = reinterpret_cast<const float4*>(Csh);

    // l=0: [AB x 1 x 128] @ [128 x 128]
    {
        const int q = tid;
        float acc[AB] = {0.f, 0.f, 0.f, 0.f};
        for (int k4 = 0; k4 < 32; k4++) {
            float4 cv[AB];
            #pragma unroll
            for (int a2 = 0; a2 < AB; a2++) cv[a2] = C4[a2 * 240 + k4];
            #pragma unroll
            for (int j = 0; j < 4; j++) {
                const float w = __ldg(L0 + (k4 * 4 + j) * 128 + q);
                #pragma unroll
                for (int a2 = 0; a2 < AB; a2++) {
                    const float c = (j == 0) ? cv[a2].x : (j == 1) ? cv[a2].y
                                  : (j == 2) ? cv[a2].z : cv[a2].w;
                    acc[a2] += c * w;
                }
            }
        }
        #pragma unroll
        for (int a2 = 0; a2 < AB; a2++) {
            const long a = a0 + a2;
            out[a * 128 + q] = __ldg(f0 + a * 128 + q) + acc[a2];
        }
    }
    // l=1: [AB x 3 x 96] @ [96 x 96]
    if (tid < 96) {
        const int q = tid;
        float acc[AB][3] = {};
        for (int k4 = 0; k4 < 24; k4++) {
            float4 cv[AB][3];
            #pragma unroll
            for (int a2 = 0; a2 < AB; a2++)
                #pragma unroll
                for (int m = 0; m < 3; m++)
                    cv[a2][m] = C4[a2 * 240 + 32 + m * 24 + k4];
            #pragma unroll
            for (int j = 0; j < 4; j++) {
                const float w = __ldg(L1 + (k4 * 4 + j) * 96 + q);
                #pragma unroll
                for (int a2 = 0; a2 < AB; a2++)
                    #pragma unroll
                    for (int m = 0; m < 3; m++) {
                        const float c = (j == 0) ? cv[a2][m].x : (j == 1) ? cv[a2][m].y
                                      : (j == 2) ? cv[a2][m].z : cv[a2][m].w;
                        acc[a2][m] += c * w;
                    }
            }
        }
        #pragma unroll
        for (int a2 = 0; a2 < AB; a2++) {
            const long a = a0 + a2;
            #pragma unroll
            for (int m = 0; m < 3; m++)
                out[1280000 + (a * 3 + m) * 96 + q] =
                    __ldg(f1 + (a * 3 + m) * 96 + q) + acc[a2][m];
        }
    }
    // l=2: [AB x 5 x 64] @ [64 x 64]
    {
        const int grp = tid >> 6, q = tid & 63;
        float acc[2][5] = {};
        for (int k4 = 0; k4 < 16; k4++) {
            const float w0 = __ldg(L2 + (k4 * 4 + 0) * 64 + q);
            const float w1 = __ldg(L2 + (k4 * 4 + 1) * 64 + q);
            const float w2 = __ldg(L2 + (k4 * 4 + 2) * 64 + q);
            const float w3 = __ldg(L2 + (k4 * 4 + 3) * 64 + q);
            #pragma unroll
            for (int j2 = 0; j2 < 2; j2++)
                #pragma unroll
                for (int m = 0; m < 5; m++) {
                    const float4 cv = C4[(grp * 2 + j2) * 240 + 104 + m * 16 + k4];
                    acc[j2][m] += cv.x * w0 + cv.y * w1 + cv.z * w2 + cv.w * w3;
                }
        }
        #pragma unroll
        for (int j2 = 0; j2 < 2; j2++) {
            const long a = a0 + grp * 2 + j2;
            #pragma unroll
            for (int m = 0; m < 5; m++)
                out[4160000 + (a * 5 + m) * 64 + q] =
                    __ldg(f2 + (a * 5 + m) * 64 + q) + acc[j2][m];
        }
    }
    // l=3: [AB x 7 x 32] @ [32 x 32]
    {
        const int grp = tid >> 5, q = tid & 31;
        float acc[7] = {};
        for (int k4 = 0; k4 < 8; k4++) {
            const float w0 = __ldg(L3 + (k4 * 4 + 0) * 32 + q);
            const float w1 = __ldg(L3 + (k4 * 4 + 1) * 32 + q);
            const float w2 = __ldg(L3 + (k4 * 4 + 2) * 32 + q);
            const float w3 = __ldg(L3 + (k4 * 4 + 3) * 32 + q);
            #pragma unroll
            for (int m = 0; m < 7; m++) {
                const float4 cv = C4[grp * 240 + 184 + m * 8 + k4];
                acc[m] += cv.x * w0 + cv.y * w1 + cv.z * w2 + cv.w * w3;
            }
        }
        const long a = a0 + grp;
        #pragma unroll
        for (int m = 0; m < 7; m++)
            out[7360000 + (a * 7 + m) * 32 + q] =
                __ldg(f3 + (a * 7 + m) * 32 + q) + acc[m];
    }
}

// ---------------------------------------------------------------------------
// Launch.  Kernel launch order: A(0), nop(1), nop(2), edge(3), out(4) —
// the profiler captures kernel index 3, i.e. k_edge this time.
// ---------------------------------------------------------------------------
extern "C" void kernel_launch(void* const* d_in, const int* in_sizes, int n_in,
                              void* d_out, int out_size)
{
    const float *r = 0, *sh0 = 0, *sh1 = 0, *sh2 = 0, *sh3 = 0;
    const float *f0 = 0, *f1 = 0, *f2 = 0, *f3 = 0;
    const float *W0 = 0, *W1 = 0, *W2 = 0, *W3 = 0;
    const float *U0 = 0, *U1 = 0, *U2 = 0, *U3 = 0;
    const float *L0 = 0, *L1 = 0, *L2 = 0, *L3 = 0;
    const int *centers = 0, *neighbors = 0;

    int n100k = 0, n1024 = 0;
    for (int i = 0; i < n_in; i++) {
        const void* p = d_in[i];
        switch (in_sizes[i]) {
            case 100000:
                if (n100k == 0)      r = (const float*)p;
                else if (n100k == 1) sh0 = (const float*)p;
                else if (n100k == 2) centers = (const int*)p;
                else                 neighbors = (const int*)p;
                n100k++;
                break;
            case 300000: sh1 = (const float*)p; break;
            case 500000: sh2 = (const float*)p; break;
            case 700000: sh3 = (const float*)p; break;
            case 1280000: f0 = (const float*)p; break;
            case 2880000: f1 = (const float*)p; break;
            case 3200000: f2 = (const float*)p; break;
            case 2240000: f3 = (const float*)p; break;
            case 768: W1 = (const float*)p; break;
            case 512: W2 = (const float*)p; break;
            case 256: W3 = (const float*)p; break;
            case 1:   U0 = (const float*)p; break;
            case 12:  U1 = (const float*)p; break;
            case 81:  U2 = (const float*)p; break;
            case 432: U3 = (const float*)p; break;
            case 16384: L0 = (const float*)p; break;
            case 9216:  L1 = (const float*)p; break;
            case 4096:  L2 = (const float*)p; break;
            case 1024:
                if (n1024 == 0) W0 = (const float*)p;
                else            L3 = (const float*)p;
                n1024++;
                break;
            default: break;
        }
    }
    float* out = (float*)d_out;

    k_uncouple_feat<<<(NATOMS * 32 + 255) / 256, 256>>>(f0, f1, f2, f3, U0, U1, U2, U3);
    k_nop<<<1, 32>>>();
    k_nop<<<1, 32>>>();
    k_edge<<<1024, 256>>>(r, sh0, sh1, sh2, sh3, W0, W1, W2, W3,
                          U0, U1, U2, U3, centers, neighbors);
    k_output<<<NATOMS / AB, 128>>>(f0, f1, f2, f3, U0, U1, U2, U3,
                                   L0, L1, L2, L3, out);
}

// round 6
// speedup vs baseline: 1.6826x; 1.1327x over previous
#include <cuda_runtime.h>

#define NATOMS 10000
#define NEDGES 100000
#define DTOT 40            // 1 + 3 + 9 + 27 uncoupled rows per atom
#define UNC 1280           // DTOT * 32 floats per atom
#define USZ 526            // 1 + 12 + 81 + 432
#define AB 4               // atoms per block in output kernel

// scratch (allocation-free rule: __device__ globals)
__device__ float g_uncf[(size_t)NATOMS * UNC];
__device__ float g_pool[(size_t)NATOMS * UNC];

__global__ void k_nop() {}

// ---------------------------------------------------------------------------
// Kernel A: zero the pool (fused) + uncouple atom features (one warp per atom)
// ---------------------------------------------------------------------------
__global__ __launch_bounds__(256)
void k_uncouple_feat(const float* __restrict__ f0, const float* __restrict__ f1,
                     const float* __restrict__ f2, const float* __restrict__ f3,
                     const float* __restrict__ U0, const float* __restrict__ U1,
                     const float* __restrict__ U2, const float* __restrict__ U3)
{
    {
        float4 z = make_float4(0.f, 0.f, 0.f, 0.f);
        float4* p = reinterpret_cast<float4*>(g_pool);
        const int n = NATOMS * UNC / 4;
        for (int i = blockIdx.x * blockDim.x + threadIdx.x; i < n;
             i += gridDim.x * blockDim.x)
            p[i] = z;
    }

    __shared__ float Ush[USZ];
    for (int i = threadIdx.x; i < USZ; i += blockDim.x) {
        float v;
        if (i < 1)       v = U0[i];
        else if (i < 13) v = U1[i - 1];
        else if (i < 94) v = U2[i - 13];
        else             v = U3[i - 94];
        Ush[i] = v;
    }
    __syncthreads();

    const int gw   = (blockIdx.x * blockDim.x + threadIdx.x) >> 5;
    const int lane = threadIdx.x & 31;
    if (gw >= NATOMS) return;
    const int a = gw;

    const float* feats[4] = {f0, f1, f2, f3};
    const int KK[4]   = {128, 96, 64, 32};
    const int LOv[4]  = {96, 64, 32, 0};
    const int DL[4]   = {1, 3, 9, 27};
    const int DOFF[4] = {0, 1, 4, 13};
    const int MLv[4]  = {1, 4, 9, 16};
    const int UOFF[4] = {0, 1, 13, 94};

    #pragma unroll
    for (int l = 0; l < 4; l++) {
        float F[16];
        int m = 0;
        #pragma unroll
        for (int lp = 0; lp <= l; lp++) {
            const float* fp = feats[lp];
            const int K = KK[lp];
            long base = (long)a * (2 * lp + 1) * K + LOv[l] + lane;
            #pragma unroll
            for (int mp = 0; mp < 2 * lp + 1; mp++)
                F[m++] = __ldg(fp + base + (long)mp * K);
        }
        float* ob = g_uncf + (long)a * UNC + DOFF[l] * 32 + lane;
        #pragma unroll
        for (int d = 0; d < DL[l]; d++) {
            float acc = 0.f;
            #pragma unroll
            for (int mm = 0; mm < MLv[l]; mm++)
                acc += Ush[UOFF[l] + d * MLv[l] + mm] * F[mm];
            ob[d * 32] = acc;
        }
    }
}

// ---------------------------------------------------------------------------
// Kernel B: warp-per-edge.  All decode/index math removed from the hot loop:
//  - Upad[160 x 16] dense masked U rows (m-major float4) -> S via 5x(4 LDS.128
//    + 16 FFMA), shv stays in registers with literal indices.
//  - Wt transposed radial weights (n-major float4) -> 10x(2 LDS.128 + 8 FFMA).
//  - Phase 2 (lane = rslot*8+ch4): float4 gather + RED.128 vector atomics.
// ---------------------------------------------------------------------------
__global__ __launch_bounds__(256)
void k_edge(const float* __restrict__ r,
            const float* __restrict__ sh0, const float* __restrict__ sh1,
            const float* __restrict__ sh2, const float* __restrict__ sh3,
            const float* __restrict__ W0, const float* __restrict__ W1,
            const float* __restrict__ W2, const float* __restrict__ W3,
            const float* __restrict__ U0, const float* __restrict__ U1,
            const float* __restrict__ U2, const float* __restrict__ U3,
            const int* __restrict__ centers, const int* __restrict__ neighbors)
{
    __shared__ __align__(16) float Upad[2560];   // [m4][p][m&3]: (m>>2)*640 + p*4 + (m&3)
    __shared__ __align__(16) float Wt[2560];     // [n4][ri][lane][n&3]
    __shared__ __align__(16) float Ssh[8 * 160]; // per-warp S rows (160, padded)
    __shared__ __align__(16) float Rsh[8 * 320]; // per-warp radv, 10 x 32ch

    const int tid = threadIdx.x;
    const int KK[4]  = {128, 96, 64, 32};
    const int LOv[4] = {96, 64, 32, 0};

    // build Upad: row p = (DOFF[l]+d)*4 + lp; value U_l[d, m] masked to
    // m in [lp^2, (lp+1)^2) (zero elsewhere / for lp > l / pad rows)
    {
        const float* Us[4] = {U0, U1, U2, U3};
        for (int idx = tid; idx < 2560; idx += 256) {
            const int p = idx >> 4, m = idx & 15;
            const int lp = p & 3, row4 = p >> 2;
            int l, d;
            if (row4 == 0)      { l = 0; d = 0; }
            else if (row4 < 4)  { l = 1; d = row4 - 1; }
            else if (row4 < 13) { l = 2; d = row4 - 4; }
            else                { l = 3; d = row4 - 13; }
            const int ml = (l + 1) * (l + 1);
            float v = 0.f;
            if (lp <= l && m >= lp * lp && m < (lp + 1) * (lp + 1) && m < ml)
                v = __ldg(Us[l] + d * ml + m);
            Upad[(m >> 2) * 640 + p * 4 + (m & 3)] = v;
        }
    }
    // build Wt: ri enumerates (l, lp<=l) in order (0,0)(1,0)(1,1)(2,0)...(3,3)
    {
        const float* Ws[4] = {W0, W1, W2, W3};
        const int riL[10]  = {0, 1, 1, 2, 2, 2, 3, 3, 3, 3};
        const int riLp[10] = {0, 0, 1, 0, 1, 2, 0, 1, 2, 3};
        for (int idx = tid; idx < 2560; idx += 256) {
            const int n = idx & 7, ln = (idx >> 3) & 31, ri = idx >> 8;
            const int l = riL[ri], lp = riLp[ri];
            Wt[((n >> 2) * 10 + ri) * 128 + ln * 4 + (n & 3)] =
                __ldg(Ws[lp] + n * KK[lp] + LOv[l] + ln);
        }
    }
    __syncthreads();

    const int lane = tid & 31;
    const int wid  = tid >> 5;
    float* Sw = Ssh + wid * 160;
    float* Rw = Rsh + wid * 320;
    const float4* Sw4 = reinterpret_cast<const float4*>(Sw);
    const float4* R4  = reinterpret_cast<const float4*>(Rw);
    const float4* Up4 = reinterpret_cast<const float4*>(Upad);
    const float4* Wt4 = reinterpret_cast<const float4*>(Wt);

    const int ch4   = lane & 7;
    const int rslot = lane >> 3;

    const int nwarp = (gridDim.x * blockDim.x) >> 5;
    const int gw0   = (blockIdx.x * blockDim.x + tid) >> 5;
    const float PI = 3.14159265358979323846f;

    for (int e = gw0; e < NEDGES; e += nwarp) {
        // ---- phase 1 ----
        const float rr = __ldg(r + e);
        const float t  = PI * (rr * 0.2f);             // pi * r / CUTOFF
        float s1, c1;
        __sincosf(t, &s1, &c1);
        const float ctc  = (t <= PI) ? c1 : -1.f;      // cos(pi*clip(x,0,1))
        const float pref = 0.5f * (ctc + 1.f) * __fdividef(1.f, rr + 1e-6f);
        float rb[8];
        rb[0] = s1 * pref;
        {
            const float twoc = 2.f * c1;
            float sp = 0.f, sc = s1;
            #pragma unroll
            for (int n = 1; n < 8; n++) {              // sin((n+1)t) recurrence
                float sn = twoc * sc - sp;
                sp = sc; sc = sn;
                rb[n] = sn * pref;
            }
        }

        float shv[16];
        shv[0] = __ldg(sh0 + e);
        #pragma unroll
        for (int mp = 0; mp < 3; mp++) shv[1 + mp] = __ldg(sh1 + (long)e * 3 + mp);
        #pragma unroll
        for (int mp = 0; mp < 5; mp++) shv[4 + mp] = __ldg(sh2 + (long)e * 5 + mp);
        #pragma unroll
        for (int mp = 0; mp < 7; mp++) shv[9 + mp] = __ldg(sh3 + (long)e * 7 + mp);

        // S rows: p = lane + 32*i, fully unrolled dense dot(16)
        #pragma unroll
        for (int i = 0; i < 5; i++) {
            const int p = lane + i * 32;
            const float4 a0 = Up4[p];
            const float4 a1 = Up4[160 + p];
            const float4 a2 = Up4[320 + p];
            const float4 a3 = Up4[480 + p];
            float s = a0.x * shv[0]  + a0.y * shv[1]  + a0.z * shv[2]  + a0.w * shv[3]
                    + a1.x * shv[4]  + a1.y * shv[5]  + a1.z * shv[6]  + a1.w * shv[7]
                    + a2.x * shv[8]  + a2.y * shv[9]  + a2.z * shv[10] + a2.w * shv[11]
                    + a3.x * shv[12] + a3.y * shv[13] + a3.z * shv[14] + a3.w * shv[15];
            Sw[p] = s;
        }

        // radial embeddings: 10 x dot(8) from transposed Wt
        #pragma unroll
        for (int ri = 0; ri < 10; ri++) {
            const float4 w0 = Wt4[ri * 32 + lane];
            const float4 w1 = Wt4[(10 + ri) * 32 + lane];
            Rw[ri * 32 + lane] =
                  rb[0] * w0.x + rb[1] * w0.y + rb[2] * w0.z + rb[3] * w0.w
                + rb[4] * w1.x + rb[5] * w1.y + rb[6] * w1.z + rb[7] * w1.w;
        }
        __syncwarp();

        // ---- phase 2: lane = (rslot, ch4), float4 over channels ----
        const int ctr = __ldg(centers + e);
        const int nbr = __ldg(neighbors + e);
        const float4* fbp = reinterpret_cast<const float4*>(g_uncf + (long)nbr * UNC);
        float*        pbp = g_pool + (long)ctr * UNC;

        #pragma unroll
        for (int rstep = 0; rstep < 10; rstep++) {
            const int row = rstep * 4 + rslot;
            const int l = (row == 0) ? 0 : (row < 4) ? 1 : (row < 13) ? 2 : 3;
            const int rbase = l * (l + 1) / 2;

            const float4 s4 = Sw4[row];
            float4 v = R4[rbase * 8 + ch4];
            float4 u;
            u.x = s4.x * v.x; u.y = s4.x * v.y; u.z = s4.x * v.z; u.w = s4.x * v.w;
            if (l >= 1) {
                v = R4[(rbase + 1) * 8 + ch4];
                u.x += s4.y * v.x; u.y += s4.y * v.y; u.z += s4.y * v.z; u.w += s4.y * v.w;
            }
            if (l >= 2) {
                v = R4[(rbase + 2) * 8 + ch4];
                u.x += s4.z * v.x; u.y += s4.z * v.y; u.z += s4.z * v.z; u.w += s4.z * v.w;
            }
            if (l >= 3) {
                v = R4[(rbase + 3) * 8 + ch4];
                u.x += s4.w * v.x; u.y += s4.w * v.y; u.z += s4.w * v.z; u.w += s4.w * v.w;
            }

            const float4 f = __ldg(fbp + row * 8 + ch4);
            const float vx = u.x * f.x, vy = u.y * f.y, vz = u.z * f.z, vw = u.w * f.w;
            asm volatile("red.global.add.v4.f32 [%0], {%1, %2, %3, %4};"
                         :: "l"(pbp + row * 32 + ch4 * 4),
                            "f"(vx), "f"(vy), "f"(vz), "f"(vw)
                         : "memory");
        }
        __syncwarp();   // protect Sw/Rw reuse across edge iterations
    }
}

// ---------------------------------------------------------------------------
// Kernel C: per atom — couple pooled with U (float4 over channels), concat,
// out = feat + cat @ Wlin.  AB atoms per 128-thread block.
// ---------------------------------------------------------------------------
__global__ __launch_bounds__(128)
void k_output(const float* __restrict__ f0, const float* __restrict__ f1,
              const float* __restrict__ f2, const float* __restrict__ f3,
              const float* __restrict__ U0, const float* __restrict__ U1,
              const float* __restrict__ U2, const float* __restrict__ U3,
              const float* __restrict__ L0, const float* __restrict__ L1,
              const float* __restrict__ L2, const float* __restrict__ L3,
              float* __restrict__ out)
{
    __shared__ float Ush[USZ];
    __shared__ __align__(16) float Psh[AB * UNC];
    __shared__ __align__(16) float Csh[AB * 960];
    const int tid = threadIdx.x;

    for (int i = tid; i < USZ; i += 128) {
        float v;
        if (i < 1)       v = U0[i];
        else if (i < 13) v = U1[i - 1];
        else if (i < 94) v = U2[i - 13];
        else             v = U3[i - 94];
        Ush[i] = v;
    }
    const int a0 = blockIdx.x * AB;
    {
        const float4* src = reinterpret_cast<const float4*>(g_pool + (long)a0 * UNC);
        float4* dst = reinterpret_cast<float4*>(Psh);
        for (int i = tid; i < AB * UNC / 4; i += 128) dst[i] = src[i];
    }
    __syncthreads();

    // couple + concat, float4 over channels: quad index q4 within 240/atom
    {
        const float4* P4 = reinterpret_cast<const float4*>(Psh);
        float4* C4w = reinterpret_cast<float4*>(Csh);
        for (int idx2 = tid; idx2 < AB * 240; idx2 += 128) {
            const int a2 = idx2 / 240;
            const int q4 = idx2 - 240 * a2;
            int l, co4, Kl4;
            if (q4 < 32)       { l = 0; co4 = 0;   Kl4 = 32; }
            else if (q4 < 104) { l = 1; co4 = 32;  Kl4 = 24; }
            else if (q4 < 184) { l = 2; co4 = 104; Kl4 = 16; }
            else               { l = 3; co4 = 184; Kl4 = 8;  }
            const int loc4 = q4 - co4;
            const int m    = loc4 / Kl4;
            const int ch4_ = loc4 - m * Kl4;
            const int b    = ch4_ >> 3;
            const int c4   = ch4_ & 7;
            const int lp   = l + b;
            const int mm   = l * l + m;
            int uo, ml, dof, dc;
            if (lp == 0)      { uo = 0;  ml = 1;  dof = 0;  dc = 1;  }
            else if (lp == 1) { uo = 1;  ml = 4;  dof = 1;  dc = 3;  }
            else if (lp == 2) { uo = 13; ml = 9;  dof = 4;  dc = 9;  }
            else              { uo = 94; ml = 16; dof = 13; dc = 27; }
            const float4* pp = P4 + a2 * 320 + dof * 8 + c4;
            const float*  uu = Ush + uo + mm;
            float4 acc = make_float4(0.f, 0.f, 0.f, 0.f);
            for (int d = 0; d < dc; d++) {
                const float u = uu[d * ml];
                const float4 pv = pp[d * 8];
                acc.x += u * pv.x; acc.y += u * pv.y;
                acc.z += u * pv.z; acc.w += u * pv.w;
            }
            C4w[idx2] = acc;
        }
    }
    __syncthreads();

    const float4* C4 = reinterpret_cast<const float4*>(Csh);

    // l=0: [AB x 1 x 128] @ [128 x 128]
    {
        const int q = tid;
        float acc[AB] = {0.f, 0.f, 0.f, 0.f};
        for (int k4 = 0; k4 < 32; k4++) {
            float4 cv[AB];
            #pragma unroll
            for (int a2 = 0; a2 < AB; a2++) cv[a2] = C4[a2 * 240 + k4];
            #pragma unroll
            for (int j = 0; j < 4; j++) {
                const float w = __ldg(L0 + (k4 * 4 + j) * 128 + q);
                #pragma unroll
                for (int a2 = 0; a2 < AB; a2++) {
                    const float c = (j == 0) ? cv[a2].x : (j == 1) ? cv[a2].y
                                  : (j == 2) ? cv[a2].z : cv[a2].w;
                    acc[a2] += c * w;
                }
            }
        }
        #pragma unroll
        for (int a2 = 0; a2 < AB; a2++) {
            const long a = a0 + a2;
            out[a * 128 + q] = __ldg(f0 + a * 128 + q) + acc[a2];
        }
    }
    // l=1: [AB x 3 x 96] @ [96 x 96]
    if (tid < 96) {
        const int q = tid;
        float acc[AB][3] = {};
        for (int k4 = 0; k4 < 24; k4++) {
            float4 cv[AB][3];
            #pragma unroll
            for (int a2 = 0; a2 < AB; a2++)
                #pragma unroll
                for (int m = 0; m < 3; m++)
                    cv[a2][m] = C4[a2 * 240 + 32 + m * 24 + k4];
            #pragma unroll
            for (int j = 0; j < 4; j++) {
                const float w = __ldg(L1 + (k4 * 4 + j) * 96 + q);
                #pragma unroll
                for (int a2 = 0; a2 < AB; a2++)
                    #pragma unroll
                    for (int m = 0; m < 3; m++) {
                        const float c = (j == 0) ? cv[a2][m].x : (j == 1) ? cv[a2][m].y
                                      : (j == 2) ? cv[a2][m].z : cv[a2][m].w;
                        acc[a2][m] += c * w;
                    }
            }
        }
        #pragma unroll
        for (int a2 = 0; a2 < AB; a2++) {
            const long a = a0 + a2;
            #pragma unroll
            for (int m = 0; m < 3; m++)
                out[1280000 + (a * 3 + m) * 96 + q] =
                    __ldg(f1 + (a * 3 + m) * 96 + q) + acc[a2][m];
        }
    }
    // l=2: [AB x 5 x 64] @ [64 x 64]
    {
        const int grp = tid >> 6, q = tid & 63;
        float acc[2][5] = {};
        for (int k4 = 0; k4 < 16; k4++) {
            const float w0 = __ldg(L2 + (k4 * 4 + 0) * 64 + q);
            const float w1 = __ldg(L2 + (k4 * 4 + 1) * 64 + q);
            const float w2 = __ldg(L2 + (k4 * 4 + 2) * 64 + q);
            const float w3 = __ldg(L2 + (k4 * 4 + 3) * 64 + q);
            #pragma unroll
            for (int j2 = 0; j2 < 2; j2++)
                #pragma unroll
                for (int m = 0; m < 5; m++) {
                    const float4 cv = C4[(grp * 2 + j2) * 240 + 104 + m * 16 + k4];
                    acc[j2][m] += cv.x * w0 + cv.y * w1 + cv.z * w2 + cv.w * w3;
                }
        }
        #pragma unroll
        for (int j2 = 0; j2 < 2; j2++) {
            const long a = a0 + grp * 2 + j2;
            #pragma unroll
            for (int m = 0; m < 5; m++)
                out[4160000 + (a * 5 + m) * 64 + q] =
                    __ldg(f2 + (a * 5 + m) * 64 + q) + acc[j2][m];
        }
    }
    // l=3: [AB x 7 x 32] @ [32 x 32]
    {
        const int grp = tid >> 5, q = tid & 31;
        float acc[7] = {};
        for (int k4 = 0; k4 < 8; k4++) {
            const float w0 = __ldg(L3 + (k4 * 4 + 0) * 32 + q);
            const float w1 = __ldg(L3 + (k4 * 4 + 1) * 32 + q);
            const float w2 = __ldg(L3 + (k4 * 4 + 2) * 32 + q);
            const float w3 = __ldg(L3 + (k4 * 4 + 3) * 32 + q);
            #pragma unroll
            for (int m = 0; m < 7; m++) {
                const float4 cv = C4[grp * 240 + 184 + m * 8 + k4];
                acc[m] += cv.x * w0 + cv.y * w1 + cv.z * w2 + cv.w * w3;
            }
        }
        const long a = a0 + grp;
        #pragma unroll
        for (int m = 0; m < 7; m++)
            out[7360000 + (a * 7 + m) * 32 + q] =
                __ldg(f3 + (a * 7 + m) * 32 + q) + acc[m];
    }
}

// ---------------------------------------------------------------------------
// Launch.  Order: A(0), edge(1), nop(2), out(3) — profiler captures launch
// index 3, i.e. k_output this round.
// ---------------------------------------------------------------------------
extern "C" void kernel_launch(void* const* d_in, const int* in_sizes, int n_in,
                              void* d_out, int out_size)
{
    const float *r = 0, *sh0 = 0, *sh1 = 0, *sh2 = 0, *sh3 = 0;
    const float *f0 = 0, *f1 = 0, *f2 = 0, *f3 = 0;
    const float *W0 = 0, *W1 = 0, *W2 = 0, *W3 = 0;
    const float *U0 = 0, *U1 = 0, *U2 = 0, *U3 = 0;
    const float *L0 = 0, *L1 = 0, *L2 = 0, *L3 = 0;
    const int *centers = 0, *neighbors = 0;

    int n100k = 0, n1024 = 0;
    for (int i = 0; i < n_in; i++) {
        const void* p = d_in[i];
        switch (in_sizes[i]) {
            case 100000:
                if (n100k == 0)      r = (const float*)p;
                else if (n100k == 1) sh0 = (const float*)p;
                else if (n100k == 2) centers = (const int*)p;
                else                 neighbors = (const int*)p;
                n100k++;
                break;
            case 300000: sh1 = (const float*)p; break;
            case 500000: sh2 = (const float*)p; break;
            case 700000: sh3 = (const float*)p; break;
            case 1280000: f0 = (const float*)p; break;
            case 2880000: f1 = (const float*)p; break;
            case 3200000: f2 = (const float*)p; break;
            case 2240000: f3 = (const float*)p; break;
            case 768: W1 = (const float*)p; break;
            case 512: W2 = (const float*)p; break;
            case 256: W3 = (const float*)p; break;
            case 1:   U0 = (const float*)p; break;
            case 12:  U1 = (const float*)p; break;
            case 81:  U2 = (const float*)p; break;
            case 432: U3 = (const float*)p; break;
            case 16384: L0 = (const float*)p; break;
            case 9216:  L1 = (const float*)p; break;
            case 4096:  L2 = (const float*)p; break;
            case 1024:
                if (n1024 == 0) W0 = (const float*)p;
                else            L3 = (const float*)p;
                n1024++;
                break;
            default: break;
        }
    }
    float* out = (float*)d_out;

    k_uncouple_feat<<<(NATOMS * 32 + 255) / 256, 256>>>(f0, f1, f2, f3, U0, U1, U2, U3);
    k_edge<<<1024, 256>>>(r, sh0, sh1, sh2, sh3, W0, W1, W2, W3,
                          U0, U1, U2, U3, centers, neighbors);
    k_nop<<<1, 32>>>();
    k_output<<<NATOMS / AB, 128>>>(f0, f1, f2, f3, U0, U1, U2, U3,
                                   L0, L1, L2, L3, out);
}

// round 7
// speedup vs baseline: 1.7580x; 1.0448x over previous
#include <cuda_runtime.h>

#define NATOMS 10000
#define NEDGES 100000
#define DTOT 40            // 1 + 3 + 9 + 27 uncoupled rows per atom
#define UNC 1280           // DTOT * 32 floats per atom
#define USZ 526            // 1 + 12 + 81 + 432
#define AB 4               // atoms per block in output kernel

// scratch (allocation-free rule: __device__ globals)
__device__ float g_uncf[(size_t)NATOMS * UNC];
__device__ float g_pool[(size_t)NATOMS * UNC];

__global__ void k_nop() {}

// ---------------------------------------------------------------------------
// Kernel A: zero the pool (fused) + uncouple atom features (one warp per atom)
// ---------------------------------------------------------------------------
__global__ __launch_bounds__(256)
void k_uncouple_feat(const float* __restrict__ f0, const float* __restrict__ f1,
                     const float* __restrict__ f2, const float* __restrict__ f3,
                     const float* __restrict__ U0, const float* __restrict__ U1,
                     const float* __restrict__ U2, const float* __restrict__ U3)
{
    {
        float4 z = make_float4(0.f, 0.f, 0.f, 0.f);
        float4* p = reinterpret_cast<float4*>(g_pool);
        const int n = NATOMS * UNC / 4;
        for (int i = blockIdx.x * blockDim.x + threadIdx.x; i < n;
             i += gridDim.x * blockDim.x)
            p[i] = z;
    }

    __shared__ float Ush[USZ];
    for (int i = threadIdx.x; i < USZ; i += blockDim.x) {
        float v;
        if (i < 1)       v = U0[i];
        else if (i < 13) v = U1[i - 1];
        else if (i < 94) v = U2[i - 13];
        else             v = U3[i - 94];
        Ush[i] = v;
    }
    __syncthreads();

    const int gw   = (blockIdx.x * blockDim.x + threadIdx.x) >> 5;
    const int lane = threadIdx.x & 31;
    if (gw >= NATOMS) return;
    const int a = gw;

    const float* feats[4] = {f0, f1, f2, f3};
    const int KK[4]   = {128, 96, 64, 32};
    const int LOv[4]  = {96, 64, 32, 0};
    const int DL[4]   = {1, 3, 9, 27};
    const int DOFF[4] = {0, 1, 4, 13};
    const int MLv[4]  = {1, 4, 9, 16};
    const int UOFF[4] = {0, 1, 13, 94};

    #pragma unroll
    for (int l = 0; l < 4; l++) {
        float F[16];
        int m = 0;
        #pragma unroll
        for (int lp = 0; lp <= l; lp++) {
            const float* fp = feats[lp];
            const int K = KK[lp];
            long base = (long)a * (2 * lp + 1) * K + LOv[l] + lane;
            #pragma unroll
            for (int mp = 0; mp < 2 * lp + 1; mp++)
                F[m++] = __ldg(fp + base + (long)mp * K);
        }
        float* ob = g_uncf + (long)a * UNC + DOFF[l] * 32 + lane;
        #pragma unroll
        for (int d = 0; d < DL[l]; d++) {
            float acc = 0.f;
            #pragma unroll
            for (int mm = 0; mm < MLv[l]; mm++)
                acc += Ush[UOFF[l] + d * MLv[l] + mm] * F[mm];
            ob[d * 32] = acc;
        }
    }
}

// ---------------------------------------------------------------------------
// Kernel B: warp-per-edge (unchanged from round 6; being profiled this round)
// ---------------------------------------------------------------------------
__global__ __launch_bounds__(256)
void k_edge(const float* __restrict__ r,
            const float* __restrict__ sh0, const float* __restrict__ sh1,
            const float* __restrict__ sh2, const float* __restrict__ sh3,
            const float* __restrict__ W0, const float* __restrict__ W1,
            const float* __restrict__ W2, const float* __restrict__ W3,
            const float* __restrict__ U0, const float* __restrict__ U1,
            const float* __restrict__ U2, const float* __restrict__ U3,
            const int* __restrict__ centers, const int* __restrict__ neighbors)
{
    __shared__ __align__(16) float Upad[2560];   // [m4][p][m&3]
    __shared__ __align__(16) float Wt[2560];     // [n4][ri][lane][n&3]
    __shared__ __align__(16) float Ssh[8 * 160]; // per-warp S rows
    __shared__ __align__(16) float Rsh[8 * 320]; // per-warp radv

    const int tid = threadIdx.x;
    const int KK[4]  = {128, 96, 64, 32};
    const int LOv[4] = {96, 64, 32, 0};

    {
        const float* Us[4] = {U0, U1, U2, U3};
        for (int idx = tid; idx < 2560; idx += 256) {
            const int p = idx >> 4, m = idx & 15;
            const int lp = p & 3, row4 = p >> 2;
            int l, d;
            if (row4 == 0)      { l = 0; d = 0; }
            else if (row4 < 4)  { l = 1; d = row4 - 1; }
            else if (row4 < 13) { l = 2; d = row4 - 4; }
            else                { l = 3; d = row4 - 13; }
            const int ml = (l + 1) * (l + 1);
            float v = 0.f;
            if (lp <= l && m >= lp * lp && m < (lp + 1) * (lp + 1) && m < ml)
                v = __ldg(Us[l] + d * ml + m);
            Upad[(m >> 2) * 640 + p * 4 + (m & 3)] = v;
        }
    }
    {
        const float* Ws[4] = {W0, W1, W2, W3};
        const int riL[10]  = {0, 1, 1, 2, 2, 2, 3, 3, 3, 3};
        const int riLp[10] = {0, 0, 1, 0, 1, 2, 0, 1, 2, 3};
        for (int idx = tid; idx < 2560; idx += 256) {
            const int n = idx & 7, ln = (idx >> 3) & 31, ri = idx >> 8;
            const int l = riL[ri], lp = riLp[ri];
            Wt[((n >> 2) * 10 + ri) * 128 + ln * 4 + (n & 3)] =
                __ldg(Ws[lp] + n * KK[lp] + LOv[l] + ln);
        }
    }
    __syncthreads();

    const int lane = tid & 31;
    const int wid  = tid >> 5;
    float* Sw = Ssh + wid * 160;
    float* Rw = Rsh + wid * 320;
    const float4* Sw4 = reinterpret_cast<const float4*>(Sw);
    const float4* R4  = reinterpret_cast<const float4*>(Rw);
    const float4* Up4 = reinterpret_cast<const float4*>(Upad);
    const float4* Wt4 = reinterpret_cast<const float4*>(Wt);

    const int ch4   = lane & 7;
    const int rslot = lane >> 3;

    const int nwarp = (gridDim.x * blockDim.x) >> 5;
    const int gw0   = (blockIdx.x * blockDim.x + tid) >> 5;
    const float PI = 3.14159265358979323846f;

    for (int e = gw0; e < NEDGES; e += nwarp) {
        const float rr = __ldg(r + e);
        const float t  = PI * (rr * 0.2f);
        float s1, c1;
        __sincosf(t, &s1, &c1);
        const float ctc  = (t <= PI) ? c1 : -1.f;
        const float pref = 0.5f * (ctc + 1.f) * __fdividef(1.f, rr + 1e-6f);
        float rb[8];
        rb[0] = s1 * pref;
        {
            const float twoc = 2.f * c1;
            float sp = 0.f, sc = s1;
            #pragma unroll
            for (int n = 1; n < 8; n++) {
                float sn = twoc * sc - sp;
                sp = sc; sc = sn;
                rb[n] = sn * pref;
            }
        }

        float shv[16];
        shv[0] = __ldg(sh0 + e);
        #pragma unroll
        for (int mp = 0; mp < 3; mp++) shv[1 + mp] = __ldg(sh1 + (long)e * 3 + mp);
        #pragma unroll
        for (int mp = 0; mp < 5; mp++) shv[4 + mp] = __ldg(sh2 + (long)e * 5 + mp);
        #pragma unroll
        for (int mp = 0; mp < 7; mp++) shv[9 + mp] = __ldg(sh3 + (long)e * 7 + mp);

        #pragma unroll
        for (int i = 0; i < 5; i++) {
            const int p = lane + i * 32;
            const float4 a0 = Up4[p];
            const float4 a1 = Up4[160 + p];
            const float4 a2 = Up4[320 + p];
            const float4 a3 = Up4[480 + p];
            float s = a0.x * shv[0]  + a0.y * shv[1]  + a0.z * shv[2]  + a0.w * shv[3]
                    + a1.x * shv[4]  + a1.y * shv[5]  + a1.z * shv[6]  + a1.w * shv[7]
                    + a2.x * shv[8]  + a2.y * shv[9]  + a2.z * shv[10] + a2.w * shv[11]
                    + a3.x * shv[12] + a3.y * shv[13] + a3.z * shv[14] + a3.w * shv[15];
            Sw[p] = s;
        }

        #pragma unroll
        for (int ri = 0; ri < 10; ri++) {
            const float4 w0 = Wt4[ri * 32 + lane];
            const float4 w1 = Wt4[(10 + ri) * 32 + lane];
            Rw[ri * 32 + lane] =
                  rb[0] * w0.x + rb[1] * w0.y + rb[2] * w0.z + rb[3] * w0.w
                + rb[4] * w1.x + rb[5] * w1.y + rb[6] * w1.z + rb[7] * w1.w;
        }
        __syncwarp();

        const int ctr = __ldg(centers + e);
        const int nbr = __ldg(neighbors + e);
        const float4* fbp = reinterpret_cast<const float4*>(g_uncf + (long)nbr * UNC);
        float*        pbp = g_pool + (long)ctr * UNC;

        #pragma unroll
        for (int rstep = 0; rstep < 10; rstep++) {
            const int row = rstep * 4 + rslot;
            const int l = (row == 0) ? 0 : (row < 4) ? 1 : (row < 13) ? 2 : 3;
            const int rbase = l * (l + 1) / 2;

            const float4 s4 = Sw4[row];
            float4 v = R4[rbase * 8 + ch4];
            float4 u;
            u.x = s4.x * v.x; u.y = s4.x * v.y; u.z = s4.x * v.z; u.w = s4.x * v.w;
            if (l >= 1) {
                v = R4[(rbase + 1) * 8 + ch4];
                u.x += s4.y * v.x; u.y += s4.y * v.y; u.z += s4.y * v.z; u.w += s4.y * v.w;
            }
            if (l >= 2) {
                v = R4[(rbase + 2) * 8 + ch4];
                u.x += s4.z * v.x; u.y += s4.z * v.y; u.z += s4.z * v.z; u.w += s4.z * v.w;
            }
            if (l >= 3) {
                v = R4[(rbase + 3) * 8 + ch4];
                u.x += s4.w * v.x; u.y += s4.w * v.y; u.z += s4.w * v.z; u.w += s4.w * v.w;
            }

            const float4 f = __ldg(fbp + row * 8 + ch4);
            const float vx = u.x * f.x, vy = u.y * f.y, vz = u.z * f.z, vw = u.w * f.w;
            asm volatile("red.global.add.v4.f32 [%0], {%1, %2, %3, %4};"
                         :: "l"(pbp + row * 32 + ch4 * 4),
                            "f"(vx), "f"(vy), "f"(vz), "f"(vw)
                         : "memory");
        }
        __syncwarp();
    }
}

// ---------------------------------------------------------------------------
// Kernel C: 256 threads/block, AB=4 atoms.  Couple stage uses all 256 threads;
// GEMM sections split across warpgroups: threads 0-127 do l0+l2 (36.9K FMA),
// threads 128-255 do l1+l3 (34.8K FMA).
// ---------------------------------------------------------------------------
__global__ __launch_bounds__(256)
void k_output(const float* __restrict__ f0, const float* __restrict__ f1,
              const float* __restrict__ f2, const float* __restrict__ f3,
              const float* __restrict__ U0, const float* __restrict__ U1,
              const float* __restrict__ U2, const float* __restrict__ U3,
              const float* __restrict__ L0, const float* __restrict__ L1,
              const float* __restrict__ L2, const float* __restrict__ L3,
              float* __restrict__ out)
{
    __shared__ float Ush[USZ];
    __shared__ __align__(16) float Psh[AB * UNC];
    __shared__ __align__(16) float Csh[AB * 960];
    const int tid = threadIdx.x;

    for (int i = tid; i < USZ; i += 256) {
        float v;
        if (i < 1)       v = U0[i];
        else if (i < 13) v = U1[i - 1];
        else if (i < 94) v = U2[i - 13];
        else             v = U3[i - 94];
        Ush[i] = v;
    }
    const int a0 = blockIdx.x * AB;
    {
        const float4* src = reinterpret_cast<const float4*>(g_pool + (long)a0 * UNC);
        float4* dst = reinterpret_cast<float4*>(Psh);
        for (int i = tid; i < AB * UNC / 4; i += 256) dst[i] = src[i];
    }
    __syncthreads();

    // couple + concat, float4 over channels
    {
        const float4* P4 = reinterpret_cast<const float4*>(Psh);
        float4* C4w = reinterpret_cast<float4*>(Csh);
        for (int idx2 = tid; idx2 < AB * 240; idx2 += 256) {
            const int a2 = idx2 / 240;
            const int q4 = idx2 - 240 * a2;
            int l, co4, Kl4;
            if (q4 < 32)       { l = 0; co4 = 0;   Kl4 = 32; }
            else if (q4 < 104) { l = 1; co4 = 32;  Kl4 = 24; }
            else if (q4 < 184) { l = 2; co4 = 104; Kl4 = 16; }
            else               { l = 3; co4 = 184; Kl4 = 8;  }
            const int loc4 = q4 - co4;
            const int m    = loc4 / Kl4;
            const int ch4_ = loc4 - m * Kl4;
            const int b    = ch4_ >> 3;
            const int c4   = ch4_ & 7;
            const int lp   = l + b;
            const int mm   = l * l + m;
            int uo, ml, dof, dc;
            if (lp == 0)      { uo = 0;  ml = 1;  dof = 0;  dc = 1;  }
            else if (lp == 1) { uo = 1;  ml = 4;  dof = 1;  dc = 3;  }
            else if (lp == 2) { uo = 13; ml = 9;  dof = 4;  dc = 9;  }
            else              { uo = 94; ml = 16; dof = 13; dc = 27; }
            const float4* pp = P4 + a2 * 320 + dof * 8 + c4;
            const float*  uu = Ush + uo + mm;
            float4 acc = make_float4(0.f, 0.f, 0.f, 0.f);
            for (int d = 0; d < dc; d++) {
                const float u = uu[d * ml];
                const float4 pv = pp[d * 8];
                acc.x += u * pv.x; acc.y += u * pv.y;
                acc.z += u * pv.z; acc.w += u * pv.w;
            }
            C4w[idx2] = acc;
        }
    }
    __syncthreads();

    const float4* C4 = reinterpret_cast<const float4*>(Csh);

    if (tid < 128) {
        // ---- l=0: [AB x 1 x 128] @ [128 x 128] ----
        {
            const int q = tid;
            float acc[AB] = {0.f, 0.f, 0.f, 0.f};
            for (int k4 = 0; k4 < 32; k4++) {
                float4 cv[AB];
                #pragma unroll
                for (int a2 = 0; a2 < AB; a2++) cv[a2] = C4[a2 * 240 + k4];
                #pragma unroll
                for (int j = 0; j < 4; j++) {
                    const float w = __ldg(L0 + (k4 * 4 + j) * 128 + q);
                    #pragma unroll
                    for (int a2 = 0; a2 < AB; a2++) {
                        const float c = (j == 0) ? cv[a2].x : (j == 1) ? cv[a2].y
                                      : (j == 2) ? cv[a2].z : cv[a2].w;
                        acc[a2] += c * w;
                    }
                }
            }
            #pragma unroll
            for (int a2 = 0; a2 < AB; a2++) {
                const long a = a0 + a2;
                out[a * 128 + q] = __ldg(f0 + a * 128 + q) + acc[a2];
            }
        }
        // ---- l=2: [AB x 5 x 64] @ [64 x 64] ----
        {
            const int grp = tid >> 6, q = tid & 63;
            float acc[2][5] = {};
            for (int k4 = 0; k4 < 16; k4++) {
                const float w0 = __ldg(L2 + (k4 * 4 + 0) * 64 + q);
                const float w1 = __ldg(L2 + (k4 * 4 + 1) * 64 + q);
                const float w2 = __ldg(L2 + (k4 * 4 + 2) * 64 + q);
                const float w3 = __ldg(L2 + (k4 * 4 + 3) * 64 + q);
                #pragma unroll
                for (int j2 = 0; j2 < 2; j2++)
                    #pragma unroll
                    for (int m = 0; m < 5; m++) {
                        const float4 cv = C4[(grp * 2 + j2) * 240 + 104 + m * 16 + k4];
                        acc[j2][m] += cv.x * w0 + cv.y * w1 + cv.z * w2 + cv.w * w3;
                    }
            }
            #pragma unroll
            for (int j2 = 0; j2 < 2; j2++) {
                const long a = a0 + grp * 2 + j2;
                #pragma unroll
                for (int m = 0; m < 5; m++)
                    out[4160000 + (a * 5 + m) * 64 + q] =
                        __ldg(f2 + (a * 5 + m) * 64 + q) + acc[j2][m];
            }
        }
    } else {
        const int tid2 = tid - 128;
        // ---- l=1: [AB x 3 x 96] @ [96 x 96] ----
        if (tid2 < 96) {
            const int q = tid2;
            float acc[AB][3] = {};
            for (int k4 = 0; k4 < 24; k4++) {
                const float w0 = __ldg(L1 + (k4 * 4 + 0) * 96 + q);
                const float w1 = __ldg(L1 + (k4 * 4 + 1) * 96 + q);
                const float w2 = __ldg(L1 + (k4 * 4 + 2) * 96 + q);
                const float w3 = __ldg(L1 + (k4 * 4 + 3) * 96 + q);
                #pragma unroll
                for (int a2 = 0; a2 < AB; a2++)
                    #pragma unroll
                    for (int m = 0; m < 3; m++) {
                        const float4 cv = C4[a2 * 240 + 32 + m * 24 + k4];
                        acc[a2][m] += cv.x * w0 + cv.y * w1 + cv.z * w2 + cv.w * w3;
                    }
            }
            #pragma unroll
            for (int a2 = 0; a2 < AB; a2++) {
                const long a = a0 + a2;
                #pragma unroll
                for (int m = 0; m < 3; m++)
                    out[1280000 + (a * 3 + m) * 96 + q] =
                        __ldg(f1 + (a * 3 + m) * 96 + q) + acc[a2][m];
            }
        }
        // ---- l=3: [AB x 7 x 32] @ [32 x 32] ----
        {
            const int grp = tid2 >> 5, q = tid2 & 31;
            float acc[7] = {};
            for (int k4 = 0; k4 < 8; k4++) {
                const float w0 = __ldg(L3 + (k4 * 4 + 0) * 32 + q);
                const float w1 = __ldg(L3 + (k4 * 4 + 1) * 32 + q);
                const float w2 = __ldg(L3 + (k4 * 4 + 2) * 32 + q);
                const float w3 = __ldg(L3 + (k4 * 4 + 3) * 32 + q);
                #pragma unroll
                for (int m = 0; m < 7; m++) {
                    const float4 cv = C4[grp * 240 + 184 + m * 8 + k4];
                    acc[m] += cv.x * w0 + cv.y * w1 + cv.z * w2 + cv.w * w3;
                }
            }
            const long a = a0 + grp;
            #pragma unroll
            for (int m = 0; m < 7; m++)
                out[7360000 + (a * 7 + m) * 32 + q] =
                    __ldg(f3 + (a * 7 + m) * 32 + q) + acc[m];
        }
    }
}

// ---------------------------------------------------------------------------
// Launch.  Order: A(0), nop(1), nop(2), edge(3), out(4) — profiler captures
// launch index 3, i.e. k_edge this round.
// ---------------------------------------------------------------------------
extern "C" void kernel_launch(void* const* d_in, const int* in_sizes, int n_in,
                              void* d_out, int out_size)
{
    const float *r = 0, *sh0 = 0, *sh1 = 0, *sh2 = 0, *sh3 = 0;
    const float *f0 = 0, *f1 = 0, *f2 = 0, *f3 = 0;
    const float *W0 = 0, *W1 = 0, *W2 = 0, *W3 = 0;
    const float *U0 = 0, *U1 = 0, *U2 = 0, *U3 = 0;
    const float *L0 = 0, *L1 = 0, *L2 = 0, *L3 = 0;
    const int *centers = 0, *neighbors = 0;

    int n100k = 0, n1024 = 0;
    for (int i = 0; i < n_in; i++) {
        const void* p = d_in[i];
        switch (in_sizes[i]) {
            case 100000:
                if (n100k == 0)      r = (const float*)p;
                else if (n100k == 1) sh0 = (const float*)p;
                else if (n100k == 2) centers = (const int*)p;
                else                 neighbors = (const int*)p;
                n100k++;
                break;
            case 300000: sh1 = (const float*)p; break;
            case 500000: sh2 = (const float*)p; break;
            case 700000: sh3 = (const float*)p; break;
            case 1280000: f0 = (const float*)p; break;
            case 2880000: f1 = (const float*)p; break;
            case 3200000: f2 = (const float*)p; break;
            case 2240000: f3 = (const float*)p; break;
            case 768: W1 = (const float*)p; break;
            case 512: W2 = (const float*)p; break;
            case 256: W3 = (const float*)p; break;
            case 1:   U0 = (const float*)p; break;
            case 12:  U1 = (const float*)p; break;
            case 81:  U2 = (const float*)p; break;
            case 432: U3 = (const float*)p; break;
            case 16384: L0 = (const float*)p; break;
            case 9216:  L1 = (const float*)p; break;
            case 4096:  L2 = (const float*)p; break;
            case 1024:
                if (n1024 == 0) W0 = (const float*)p;
                else            L3 = (const float*)p;
                n1024++;
                break;
            default: break;
        }
    }
    float* out = (float*)d_out;

    k_uncouple_feat<<<(NATOMS * 32 + 255) / 256, 256>>>(f0, f1, f2, f3, U0, U1, U2, U3);
    k_nop<<<1, 32>>>();
    k_nop<<<1, 32>>>();
    k_edge<<<1024, 256>>>(r, sh0, sh1, sh2, sh3, W0, W1, W2, W3,
                          U0, U1, U2, U3, centers, neighbors);
    k_output<<<NATOMS / AB, 256>>>(f0, f1, f2, f3, U0, U1, U2, U3,
                                   L0, L1, L2, L3, out);
}

// round 8
// speedup vs baseline: 1.9432x; 1.1054x over previous
#include <cuda_runtime.h>

#define NATOMS 10000
#define NEDGES 100000
#define DTOT 40            // 1 + 3 + 9 + 27 uncoupled rows per atom
#define UNC 1280           // DTOT * 32 floats per atom
#define USZ 526            // 1 + 12 + 81 + 432
#define AB 4               // atoms per block in output kernel

// scratch (allocation-free rule: __device__ globals)
__device__ float g_uncf[(size_t)NATOMS * UNC];
__device__ float g_pool[(size_t)NATOMS * UNC];

__global__ void k_nop() {}

__device__ __forceinline__ float dot4(const float4 a, const float4 b) {
    return a.x * b.x + a.y * b.y + a.z * b.z + a.w * b.w;
}

// ---------------------------------------------------------------------------
// Kernel A: zero the pool (fused) + uncouple atom features (one warp per atom)
// ---------------------------------------------------------------------------
__global__ __launch_bounds__(256)
void k_uncouple_feat(const float* __restrict__ f0, const float* __restrict__ f1,
                     const float* __restrict__ f2, const float* __restrict__ f3,
                     const float* __restrict__ U0, const float* __restrict__ U1,
                     const float* __restrict__ U2, const float* __restrict__ U3)
{
    {
        float4 z = make_float4(0.f, 0.f, 0.f, 0.f);
        float4* p = reinterpret_cast<float4*>(g_pool);
        const int n = NATOMS * UNC / 4;
        for (int i = blockIdx.x * blockDim.x + threadIdx.x; i < n;
             i += gridDim.x * blockDim.x)
            p[i] = z;
    }

    __shared__ float Ush[USZ];
    for (int i = threadIdx.x; i < USZ; i += blockDim.x) {
        float v;
        if (i < 1)       v = U0[i];
        else if (i < 13) v = U1[i - 1];
        else if (i < 94) v = U2[i - 13];
        else             v = U3[i - 94];
        Ush[i] = v;
    }
    __syncthreads();

    const int gw   = (blockIdx.x * blockDim.x + threadIdx.x) >> 5;
    const int lane = threadIdx.x & 31;
    if (gw >= NATOMS) return;
    const int a = gw;

    const float* feats[4] = {f0, f1, f2, f3};
    const int KK[4]   = {128, 96, 64, 32};
    const int LOv[4]  = {96, 64, 32, 0};
    const int DL[4]   = {1, 3, 9, 27};
    const int DOFF[4] = {0, 1, 4, 13};
    const int MLv[4]  = {1, 4, 9, 16};
    const int UOFF[4] = {0, 1, 13, 94};

    #pragma unroll
    for (int l = 0; l < 4; l++) {
        float F[16];
        int m = 0;
        #pragma unroll
        for (int lp = 0; lp <= l; lp++) {
            const float* fp = feats[lp];
            const int K = KK[lp];
            long base = (long)a * (2 * lp + 1) * K + LOv[l] + lane;
            #pragma unroll
            for (int mp = 0; mp < 2 * lp + 1; mp++)
                F[m++] = __ldg(fp + base + (long)mp * K);
        }
        float* ob = g_uncf + (long)a * UNC + DOFF[l] * 32 + lane;
        #pragma unroll
        for (int d = 0; d < DL[l]; d++) {
            float acc = 0.f;
            #pragma unroll
            for (int mm = 0; mm < MLv[l]; mm++)
                acc += Ush[UOFF[l] + d * MLv[l] + mm] * F[mm];
            ob[d * 32] = acc;
        }
    }
}

// ---------------------------------------------------------------------------
// Kernel B: warp-per-EDGE-PAIR.  Weight tables (compact Upad2 + Wt) are read
// once per pair and dotted against both edges' shv/rb -> weight shared-read
// traffic per edge halved.  Upad2 compacted to an 8-col window per row
// (lane&3 == lp fixed), stride 12 floats for conflict-free banks.
// ---------------------------------------------------------------------------
__global__ __launch_bounds__(256)
void k_edge(const float* __restrict__ r,
            const float* __restrict__ sh0, const float* __restrict__ sh1,
            const float* __restrict__ sh2, const float* __restrict__ sh3,
            const float* __restrict__ W0, const float* __restrict__ W1,
            const float* __restrict__ W2, const float* __restrict__ W3,
            const float* __restrict__ U0, const float* __restrict__ U1,
            const float* __restrict__ U2, const float* __restrict__ U3,
            const int* __restrict__ centers, const int* __restrict__ neighbors)
{
    __shared__ __align__(16) float Upad2[160 * 12];   // [p][12], cols window base[lp]
    __shared__ __align__(16) float Wt[2560];          // [n4][ri][lane][n&3]
    __shared__ __align__(16) float Ssh[8 * 2 * 160];  // per-warp, 2 edge buffers
    __shared__ __align__(16) float Rsh[8 * 2 * 320];  // per-warp, 2 edge buffers

    const int tid = threadIdx.x;
    const int KK[4]  = {128, 96, 64, 32};
    const int LOv[4] = {96, 64, 32, 0};

    // build compact Upad2
    {
        const float* Us[4] = {U0, U1, U2, U3};
        const int baseT[4] = {0, 0, 4, 8};
        for (int idx = tid; idx < 160 * 12; idx += 256) {
            const int p = idx / 12, c = idx - p * 12;
            const int lp = p & 3, row4 = p >> 2;
            int l, d;
            if (row4 == 0)      { l = 0; d = 0; }
            else if (row4 < 4)  { l = 1; d = row4 - 1; }
            else if (row4 < 13) { l = 2; d = row4 - 4; }
            else                { l = 3; d = row4 - 13; }
            const int ml = (l + 1) * (l + 1);
            const int m = baseT[lp] + c;
            float v = 0.f;
            if (c < 8 && lp <= l && m >= lp * lp && m < (lp + 1) * (lp + 1) && m < ml)
                v = __ldg(Us[l] + d * ml + m);
            Upad2[idx] = v;
        }
    }
    // build Wt
    {
        const float* Ws[4] = {W0, W1, W2, W3};
        const int riL[10]  = {0, 1, 1, 2, 2, 2, 3, 3, 3, 3};
        const int riLp[10] = {0, 0, 1, 0, 1, 2, 0, 1, 2, 3};
        for (int idx = tid; idx < 2560; idx += 256) {
            const int n = idx & 7, ln = (idx >> 3) & 31, ri = idx >> 8;
            const int l = riL[ri], lp = riLp[ri];
            Wt[((n >> 2) * 10 + ri) * 128 + ln * 4 + (n & 3)] =
                __ldg(Ws[lp] + n * KK[lp] + LOv[l] + ln);
        }
    }
    __syncthreads();

    const int lane = tid & 31;
    const int wid  = tid >> 5;
    const int lp4  = lane & 3;
    float* Sw0 = Ssh + wid * 320;
    float* Sw1 = Sw0 + 160;
    float* Rw0 = Rsh + wid * 640;
    float* Rw1 = Rw0 + 320;
    const float4* S0_4 = reinterpret_cast<const float4*>(Sw0);
    const float4* S1_4 = reinterpret_cast<const float4*>(Sw1);
    const float4* R0_4 = reinterpret_cast<const float4*>(Rw0);
    const float4* R1_4 = reinterpret_cast<const float4*>(Rw1);
    const float4* Up2  = reinterpret_cast<const float4*>(Upad2);
    const float4* Wt4  = reinterpret_cast<const float4*>(Wt);

    const int ch4   = lane & 7;
    const int rslot = lane >> 3;

    const int nwarp = (gridDim.x * blockDim.x) >> 5;
    const int gw0   = (blockIdx.x * blockDim.x + tid) >> 5;
    const float PI = 3.14159265358979323846f;

    for (int ep = gw0; ep < NEDGES / 2; ep += nwarp) {
        const int e0 = ep * 2, e1 = e0 + 1;

        // radial bases for both edges
        float rb0[8], rb1[8];
        #pragma unroll
        for (int k = 0; k < 2; k++) {
            const int e = k ? e1 : e0;
            float* rb = k ? rb1 : rb0;
            const float rr = __ldg(r + e);
            const float t  = PI * (rr * 0.2f);
            float s1, c1;
            __sincosf(t, &s1, &c1);
            const float ctc  = (t <= PI) ? c1 : -1.f;
            const float pref = 0.5f * (ctc + 1.f) * __fdividef(1.f, rr + 1e-6f);
            rb[0] = s1 * pref;
            const float twoc = 2.f * c1;
            float sp = 0.f, sc = s1;
            #pragma unroll
            for (int n = 1; n < 8; n++) {
                float sn = twoc * sc - sp;
                sp = sc; sc = sn;
                rb[n] = sn * pref;
            }
        }

        // spherical harmonics, packed as float4 quads shv[0..3|4..7|8..11|12..15]
        float4 q00, q01, q02, q03, q10, q11, q12, q13;
        q00.x = __ldg(sh0 + e0);
        q00.y = __ldg(sh1 + (long)e0 * 3 + 0);
        q00.z = __ldg(sh1 + (long)e0 * 3 + 1);
        q00.w = __ldg(sh1 + (long)e0 * 3 + 2);
        q01.x = __ldg(sh2 + (long)e0 * 5 + 0);
        q01.y = __ldg(sh2 + (long)e0 * 5 + 1);
        q01.z = __ldg(sh2 + (long)e0 * 5 + 2);
        q01.w = __ldg(sh2 + (long)e0 * 5 + 3);
        q02.x = __ldg(sh2 + (long)e0 * 5 + 4);
        q02.y = __ldg(sh3 + (long)e0 * 7 + 0);
        q02.z = __ldg(sh3 + (long)e0 * 7 + 1);
        q02.w = __ldg(sh3 + (long)e0 * 7 + 2);
        q03.x = __ldg(sh3 + (long)e0 * 7 + 3);
        q03.y = __ldg(sh3 + (long)e0 * 7 + 4);
        q03.z = __ldg(sh3 + (long)e0 * 7 + 5);
        q03.w = __ldg(sh3 + (long)e0 * 7 + 6);
        q10.x = __ldg(sh0 + e1);
        q10.y = __ldg(sh1 + (long)e1 * 3 + 0);
        q10.z = __ldg(sh1 + (long)e1 * 3 + 1);
        q10.w = __ldg(sh1 + (long)e1 * 3 + 2);
        q11.x = __ldg(sh2 + (long)e1 * 5 + 0);
        q11.y = __ldg(sh2 + (long)e1 * 5 + 1);
        q11.z = __ldg(sh2 + (long)e1 * 5 + 2);
        q11.w = __ldg(sh2 + (long)e1 * 5 + 3);
        q12.x = __ldg(sh2 + (long)e1 * 5 + 4);
        q12.y = __ldg(sh3 + (long)e1 * 7 + 0);
        q12.z = __ldg(sh3 + (long)e1 * 7 + 1);
        q12.w = __ldg(sh3 + (long)e1 * 7 + 2);
        q13.x = __ldg(sh3 + (long)e1 * 7 + 3);
        q13.y = __ldg(sh3 + (long)e1 * 7 + 4);
        q13.z = __ldg(sh3 + (long)e1 * 7 + 5);
        q13.w = __ldg(sh3 + (long)e1 * 7 + 6);

        // per-lane shv window select (lp fixed per lane): base {0,0,4,8}
        float4 sA0, sB0, sA1, sB1;
        if (lp4 < 2)       { sA0 = q00; sB0 = q01; sA1 = q10; sB1 = q11; }
        else if (lp4 == 2) { sA0 = q01; sB0 = q02; sA1 = q11; sB1 = q12; }
        else               { sA0 = q02; sB0 = q03; sA1 = q12; sB1 = q13; }

        // S rows for both edges: weight float4s read ONCE, used twice
        #pragma unroll
        for (int i = 0; i < 5; i++) {
            const int p = lane + i * 32;
            const float4 a0 = Up2[p * 3];
            const float4 a1 = Up2[p * 3 + 1];
            Sw0[p] = dot4(a0, sA0) + dot4(a1, sB0);
            Sw1[p] = dot4(a0, sA1) + dot4(a1, sB1);
        }

        // radial embeddings for both edges: Wt read once, two dots
        #pragma unroll
        for (int ri = 0; ri < 10; ri++) {
            const float4 w0 = Wt4[ri * 32 + lane];
            const float4 w1 = Wt4[(10 + ri) * 32 + lane];
            Rw0[ri * 32 + lane] =
                  rb0[0] * w0.x + rb0[1] * w0.y + rb0[2] * w0.z + rb0[3] * w0.w
                + rb0[4] * w1.x + rb0[5] * w1.y + rb0[6] * w1.z + rb0[7] * w1.w;
            Rw1[ri * 32 + lane] =
                  rb1[0] * w0.x + rb1[1] * w0.y + rb1[2] * w0.z + rb1[3] * w0.w
                + rb1[4] * w1.x + rb1[5] * w1.y + rb1[6] * w1.z + rb1[7] * w1.w;
        }
        __syncwarp();

        // ---- phase 2: lane = (rslot, ch4), both edges interleaved ----
        const int ctr0 = __ldg(centers + e0);
        const int nbr0 = __ldg(neighbors + e0);
        const int ctr1 = __ldg(centers + e1);
        const int nbr1 = __ldg(neighbors + e1);
        const float4* fbp0 = reinterpret_cast<const float4*>(g_uncf + (long)nbr0 * UNC);
        const float4* fbp1 = reinterpret_cast<const float4*>(g_uncf + (long)nbr1 * UNC);
        float* pbp0 = g_pool + (long)ctr0 * UNC;
        float* pbp1 = g_pool + (long)ctr1 * UNC;

        #pragma unroll
        for (int rstep = 0; rstep < 10; rstep++) {
            const int row = rstep * 4 + rslot;
            const int l = (row == 0) ? 0 : (row < 4) ? 1 : (row < 13) ? 2 : 3;
            const int rbase = l * (l + 1) / 2;

            const float4 sa = S0_4[row];
            const float4 sb = S1_4[row];
            float4 v0 = R0_4[rbase * 8 + ch4];
            float4 v1 = R1_4[rbase * 8 + ch4];
            float4 uA, uB;
            uA.x = sa.x * v0.x; uA.y = sa.x * v0.y; uA.z = sa.x * v0.z; uA.w = sa.x * v0.w;
            uB.x = sb.x * v1.x; uB.y = sb.x * v1.y; uB.z = sb.x * v1.z; uB.w = sb.x * v1.w;
            if (l >= 1) {
                v0 = R0_4[(rbase + 1) * 8 + ch4];
                v1 = R1_4[(rbase + 1) * 8 + ch4];
                uA.x += sa.y * v0.x; uA.y += sa.y * v0.y; uA.z += sa.y * v0.z; uA.w += sa.y * v0.w;
                uB.x += sb.y * v1.x; uB.y += sb.y * v1.y; uB.z += sb.y * v1.z; uB.w += sb.y * v1.w;
            }
            if (l >= 2) {
                v0 = R0_4[(rbase + 2) * 8 + ch4];
                v1 = R1_4[(rbase + 2) * 8 + ch4];
                uA.x += sa.z * v0.x; uA.y += sa.z * v0.y; uA.z += sa.z * v0.z; uA.w += sa.z * v0.w;
                uB.x += sb.z * v1.x; uB.y += sb.z * v1.y; uB.z += sb.z * v1.z; uB.w += sb.z * v1.w;
            }
            if (l >= 3) {
                v0 = R0_4[(rbase + 3) * 8 + ch4];
                v1 = R1_4[(rbase + 3) * 8 + ch4];
                uA.x += sa.w * v0.x; uA.y += sa.w * v0.y; uA.z += sa.w * v0.z; uA.w += sa.w * v0.w;
                uB.x += sb.w * v1.x; uB.y += sb.w * v1.y; uB.z += sb.w * v1.z; uB.w += sb.w * v1.w;
            }

            const float4 fA = __ldg(fbp0 + row * 8 + ch4);
            const float4 fB = __ldg(fbp1 + row * 8 + ch4);
            const float ax = uA.x * fA.x, ay = uA.y * fA.y, az = uA.z * fA.z, aw = uA.w * fA.w;
            const float bx = uB.x * fB.x, by = uB.y * fB.y, bz = uB.z * fB.z, bw = uB.w * fB.w;
            asm volatile("red.global.add.v4.f32 [%0], {%1, %2, %3, %4};"
                         :: "l"(pbp0 + row * 32 + ch4 * 4),
                            "f"(ax), "f"(ay), "f"(az), "f"(aw) : "memory");
            asm volatile("red.global.add.v4.f32 [%0], {%1, %2, %3, %4};"
                         :: "l"(pbp1 + row * 32 + ch4 * 4),
                            "f"(bx), "f"(by), "f"(bz), "f"(bw) : "memory");
        }
        __syncwarp();   // protect S/R buffers before next pair
    }
}

// ---------------------------------------------------------------------------
// Kernel C: 256 threads/block, AB=4 atoms; GEMMs split across warpgroups.
// ---------------------------------------------------------------------------
__global__ __launch_bounds__(256)
void k_output(const float* __restrict__ f0, const float* __restrict__ f1,
              const float* __restrict__ f2, const float* __restrict__ f3,
              const float* __restrict__ U0, const float* __restrict__ U1,
              const float* __restrict__ U2, const float* __restrict__ U3,
              const float* __restrict__ L0, const float* __restrict__ L1,
              const float* __restrict__ L2, const float* __restrict__ L3,
              float* __restrict__ out)
{
    __shared__ float Ush[USZ];
    __shared__ __align__(16) float Psh[AB * UNC];
    __shared__ __align__(16) float Csh[AB * 960];
    const int tid = threadIdx.x;

    for (int i = tid; i < USZ; i += 256) {
        float v;
        if (i < 1)       v = U0[i];
        else if (i < 13) v = U1[i - 1];
        else if (i < 94) v = U2[i - 13];
        else             v = U3[i - 94];
        Ush[i] = v;
    }
    const int a0 = blockIdx.x * AB;
    {
        const float4* src = reinterpret_cast<const float4*>(g_pool + (long)a0 * UNC);
        float4* dst = reinterpret_cast<float4*>(Psh);
        for (int i = tid; i < AB * UNC / 4; i += 256) dst[i] = src[i];
    }
    __syncthreads();

    {
        const float4* P4 = reinterpret_cast<const float4*>(Psh);
        float4* C4w = reinterpret_cast<float4*>(Csh);
        for (int idx2 = tid; idx2 < AB * 240; idx2 += 256) {
            const int a2 = idx2 / 240;
            const int q4 = idx2 - 240 * a2;
            int l, co4, Kl4;
            if (q4 < 32)       { l = 0; co4 = 0;   Kl4 = 32; }
            else if (q4 < 104) { l = 1; co4 = 32;  Kl4 = 24; }
            else if (q4 < 184) { l = 2; co4 = 104; Kl4 = 16; }
            else               { l = 3; co4 = 184; Kl4 = 8;  }
            const int loc4 = q4 - co4;
            const int m    = loc4 / Kl4;
            const int ch4_ = loc4 - m * Kl4;
            const int b    = ch4_ >> 3;
            const int c4   = ch4_ & 7;
            const int lp   = l + b;
            const int mm   = l * l + m;
            int uo, ml, dof, dc;
            if (lp == 0)      { uo = 0;  ml = 1;  dof = 0;  dc = 1;  }
            else if (lp == 1) { uo = 1;  ml = 4;  dof = 1;  dc = 3;  }
            else if (lp == 2) { uo = 13; ml = 9;  dof = 4;  dc = 9;  }
            else              { uo = 94; ml = 16; dof = 13; dc = 27; }
            const float4* pp = P4 + a2 * 320 + dof * 8 + c4;
            const float*  uu = Ush + uo + mm;
            float4 acc = make_float4(0.f, 0.f, 0.f, 0.f);
            for (int d = 0; d < dc; d++) {
                const float u = uu[d * ml];
                const float4 pv = pp[d * 8];
                acc.x += u * pv.x; acc.y += u * pv.y;
                acc.z += u * pv.z; acc.w += u * pv.w;
            }
            C4w[idx2] = acc;
        }
    }
    __syncthreads();

    const float4* C4 = reinterpret_cast<const float4*>(Csh);

    if (tid < 128) {
        {
            const int q = tid;
            float acc[AB] = {0.f, 0.f, 0.f, 0.f};
            for (int k4 = 0; k4 < 32; k4++) {
                float4 cv[AB];
                #pragma unroll
                for (int a2 = 0; a2 < AB; a2++) cv[a2] = C4[a2 * 240 + k4];
                #pragma unroll
                for (int j = 0; j < 4; j++) {
                    const float w = __ldg(L0 + (k4 * 4 + j) * 128 + q);
                    #pragma unroll
                    for (int a2 = 0; a2 < AB; a2++) {
                        const float c = (j == 0) ? cv[a2].x : (j == 1) ? cv[a2].y
                                      : (j == 2) ? cv[a2].z : cv[a2].w;
                        acc[a2] += c * w;
                    }
                }
            }
            #pragma unroll
            for (int a2 = 0; a2 < AB; a2++) {
                const long a = a0 + a2;
                out[a * 128 + q] = __ldg(f0 + a * 128 + q) + acc[a2];
            }
        }
        {
            const int grp = tid >> 6, q = tid & 63;
            float acc[2][5] = {};
            for (int k4 = 0; k4 < 16; k4++) {
                const float w0 = __ldg(L2 + (k4 * 4 + 0) * 64 + q);
                const float w1 = __ldg(L2 + (k4 * 4 + 1) * 64 + q);
                const float w2 = __ldg(L2 + (k4 * 4 + 2) * 64 + q);
                const float w3 = __ldg(L2 + (k4 * 4 + 3) * 64 + q);
                #pragma unroll
                for (int j2 = 0; j2 < 2; j2++)
                    #pragma unroll
                    for (int m = 0; m < 5; m++) {
                        const float4 cv = C4[(grp * 2 + j2) * 240 + 104 + m * 16 + k4];
                        acc[j2][m] += cv.x * w0 + cv.y * w1 + cv.z * w2 + cv.w * w3;
                    }
            }
            #pragma unroll
            for (int j2 = 0; j2 < 2; j2++) {
                const long a = a0 + grp * 2 + j2;
                #pragma unroll
                for (int m = 0; m < 5; m++)
                    out[4160000 + (a * 5 + m) * 64 + q] =
                        __ldg(f2 + (a * 5 + m) * 64 + q) + acc[j2][m];
            }
        }
    } else {
        const int tid2 = tid - 128;
        if (tid2 < 96) {
            const int q = tid2;
            float acc[AB][3] = {};
            for (int k4 = 0; k4 < 24; k4++) {
                const float w0 = __ldg(L1 + (k4 * 4 + 0) * 96 + q);
                const float w1 = __ldg(L1 + (k4 * 4 + 1) * 96 + q);
                const float w2 = __ldg(L1 + (k4 * 4 + 2) * 96 + q);
                const float w3 = __ldg(L1 + (k4 * 4 + 3) * 96 + q);
                #pragma unroll
                for (int a2 = 0; a2 < AB; a2++)
                    #pragma unroll
                    for (int m = 0; m < 3; m++) {
                        const float4 cv = C4[a2 * 240 + 32 + m * 24 + k4];
                        acc[a2][m] += cv.x * w0 + cv.y * w1 + cv.z * w2 + cv.w * w3;
                    }
            }
            #pragma unroll
            for (int a2 = 0; a2 < AB; a2++) {
                const long a = a0 + a2;
                #pragma unroll
                for (int m = 0; m < 3; m++)
                    out[1280000 + (a * 3 + m) * 96 + q] =
                        __ldg(f1 + (a * 3 + m) * 96 + q) + acc[a2][m];
            }
        }
        {
            const int grp = tid2 >> 5, q = tid2 & 31;
            float acc[7] = {};
            for (int k4 = 0; k4 < 8; k4++) {
                const float w0 = __ldg(L3 + (k4 * 4 + 0) * 32 + q);
                const float w1 = __ldg(L3 + (k4 * 4 + 1) * 32 + q);
                const float w2 = __ldg(L3 + (k4 * 4 + 2) * 32 + q);
                const float w3 = __ldg(L3 + (k4 * 4 + 3) * 32 + q);
                #pragma unroll
                for (int m = 0; m < 7; m++) {
                    const float4 cv = C4[grp * 240 + 184 + m * 8 + k4];
                    acc[m] += cv.x * w0 + cv.y * w1 + cv.z * w2 + cv.w * w3;
                }
            }
            const long a = a0 + grp;
            #pragma unroll
            for (int m = 0; m < 7; m++)
                out[7360000 + (a * 7 + m) * 32 + q] =
                    __ldg(f3 + (a * 7 + m) * 32 + q) + acc[m];
        }
    }
}

// ---------------------------------------------------------------------------
// Launch.  Order: A(0), nop(1), nop(2), edge(3), out(4) — profiler captures
// launch index 3 (k_edge).
// ---------------------------------------------------------------------------
extern "C" void kernel_launch(void* const* d_in, const int* in_sizes, int n_in,
                              void* d_out, int out_size)
{
    const float *r = 0, *sh0 = 0, *sh1 = 0, *sh2 = 0, *sh3 = 0;
    const float *f0 = 0, *f1 = 0, *f2 = 0, *f3 = 0;
    const float *W0 = 0, *W1 = 0, *W2 = 0, *W3 = 0;
    const float *U0 = 0, *U1 = 0, *U2 = 0, *U3 = 0;
    const float *L0 = 0, *L1 = 0, *L2 = 0, *L3 = 0;
    const int *centers = 0, *neighbors = 0;

    int n100k = 0, n1024 = 0;
    for (int i = 0; i < n_in; i++) {
        const void* p = d_in[i];
        switch (in_sizes[i]) {
            case 100000:
                if (n100k == 0)      r = (const float*)p;
                else if (n100k == 1) sh0 = (const float*)p;
                else if (n100k == 2) centers = (const int*)p;
                else                 neighbors = (const int*)p;
                n100k++;
                break;
            case 300000: sh1 = (const float*)p; break;
            case 500000: sh2 = (const float*)p; break;
            case 700000: sh3 = (const float*)p; break;
            case 1280000: f0 = (const float*)p; break;
            case 2880000: f1 = (const float*)p; break;
            case 3200000: f2 = (const float*)p; break;
            case 2240000: f3 = (const float*)p; break;
            case 768: W1 = (const float*)p; break;
            case 512: W2 = (const float*)p; break;
            case 256: W3 = (const float*)p; break;
            case 1:   U0 = (const float*)p; break;
            case 12:  U1 = (const float*)p; break;
            case 81:  U2 = (const float*)p; break;
            case 432: U3 = (const float*)p; break;
            case 16384: L0 = (const float*)p; break;
            case 9216:  L1 = (const float*)p; break;
            case 4096:  L2 = (const float*)p; break;
            case 1024:
                if (n1024 == 0) W0 = (const float*)p;
                else            L3 = (const float*)p;
                n1024++;
                break;
            default: break;
        }
    }
    float* out = (float*)d_out;

    k_uncouple_feat<<<(NATOMS * 32 + 255) / 256, 256>>>(f0, f1, f2, f3, U0, U1, U2, U3);
    k_nop<<<1, 32>>>();
    k_nop<<<1, 32>>>();
    k_edge<<<1024, 256>>>(r, sh0, sh1, sh2, sh3, W0, W1, W2, W3,
                          U0, U1, U2, U3, centers, neighbors);
    k_output<<<NATOMS / AB, 256>>>(f0, f1, f2, f3, U0, U1, U2, U3,
                                   L0, L1, L2, L3, out);
}